// round 2
// baseline (speedup 1.0000x reference)
#include <cuda_runtime.h>
#include <cstddef>

// Problem constants
#define B_   4
#define N_   4096
#define E_   256
#define F_   256      // F_IN == F_OUT
#define MAXE 50
#define H1_  128
#define H2_  64
#define OUTC 512      // E_ + F_OUT

// ---------------------------------------------------------------------------
// Static device scratch (no dynamic allocation allowed)
// ---------------------------------------------------------------------------
__device__ float g_xp[B_ * N_ * F_];          // x @ Wn_w + Wn_b        (16 MB)
__device__ float g_v [B_ * N_ * F_];          // x @ weight             (16 MB)
__device__ float g_S [67108864];              // [B][4096][4096] scores (256 MB)
__device__ float g_mean[B_ * MAXE * F_];      // per-edge mean features
__device__ float g_ctx [B_ * MAXE];           // MLP context scalar per (b,e)
__device__ float g_deg [MAXE];                // edge degrees (float)

// ---------------------------------------------------------------------------
// SGEMM config: 128x128 tile, BK=8, 8x8 per thread, 256 threads
// All dims used are multiples of the tile sizes -> no bounds checks.
// ---------------------------------------------------------------------------
#define BM 128
#define BN 128
#define BK 8
#define TM 8
#define TN 8

// C[z] = A[z](MxK) * B[z](KxN) * scale + bias  (B row-major, bias may be null)
__global__ __launch_bounds__(256)
void sgemm_nn(const float* __restrict__ A, const float* __restrict__ Bm,
              const float* __restrict__ bias, float* __restrict__ C,
              int M, int N, int K, int lda, int ldb, int ldc,
              size_t sA, size_t sB, size_t sC, float scale)
{
    __shared__ float As[BK][BM];
    __shared__ float Bs[BK][BN];
    const int tid = threadIdx.x;

    A  += (size_t)blockIdx.z * sA + (size_t)blockIdx.y * BM * lda;
    Bm += (size_t)blockIdx.z * sB + (size_t)blockIdx.x * BN;
    C  += (size_t)blockIdx.z * sC + (size_t)blockIdx.y * BM * ldc
        + (size_t)blockIdx.x * BN;

    const int arow = tid >> 1, acol = (tid & 1) << 2;   // A tile: 128 x 8
    const int brow = tid >> 5, bcol = (tid & 31) << 2;  // B tile: 8 x 128
    const int trow = (tid >> 4) * TM;
    const int tcol = (tid & 15) * TN;

    float acc[TM][TN];
#pragma unroll
    for (int i = 0; i < TM; i++)
#pragma unroll
        for (int j = 0; j < TN; j++) acc[i][j] = 0.f;

    for (int k0 = 0; k0 < K; k0 += BK) {
        float4 a = *(const float4*)(A + (size_t)arow * lda + k0 + acol);
        As[acol + 0][arow] = a.x;
        As[acol + 1][arow] = a.y;
        As[acol + 2][arow] = a.z;
        As[acol + 3][arow] = a.w;
        float4 b = *(const float4*)(Bm + (size_t)(k0 + brow) * ldb + bcol);
        *(float4*)&Bs[brow][bcol] = b;
        __syncthreads();
#pragma unroll
        for (int kk = 0; kk < BK; kk++) {
            float ra[TM], rb[TN];
            *(float4*)&ra[0] = *(const float4*)&As[kk][trow];
            *(float4*)&ra[4] = *(const float4*)&As[kk][trow + 4];
            *(float4*)&rb[0] = *(const float4*)&Bs[kk][tcol];
            *(float4*)&rb[4] = *(const float4*)&Bs[kk][tcol + 4];
#pragma unroll
            for (int i = 0; i < TM; i++)
#pragma unroll
                for (int j = 0; j < TN; j++)
                    acc[i][j] = fmaf(ra[i], rb[j], acc[i][j]);
        }
        __syncthreads();
    }

#pragma unroll
    for (int i = 0; i < TM; i++) {
        float o[TN];
#pragma unroll
        for (int j = 0; j < TN; j++) {
            o[j] = acc[i][j] * scale;
            if (bias) o[j] += bias[(size_t)blockIdx.x * BN + tcol + j];
        }
        float* Cr = C + (size_t)(trow + i) * ldc + tcol;
        *(float4*)Cr       = *(float4*)&o[0];
        *(float4*)(Cr + 4) = *(float4*)&o[4];
    }
}

// C[z] = A[z](MxK) * B[z](NxK)^T * scale
__global__ __launch_bounds__(256)
void sgemm_nt(const float* __restrict__ A, const float* __restrict__ Bm,
              float* __restrict__ C,
              int M, int N, int K, int lda, int ldb, int ldc,
              size_t sA, size_t sB, size_t sC, float scale)
{
    __shared__ float As[BK][BM];
    __shared__ float Bs[BK][BN];
    const int tid = threadIdx.x;

    A  += (size_t)blockIdx.z * sA + (size_t)blockIdx.y * BM * lda;
    Bm += (size_t)blockIdx.z * sB + (size_t)blockIdx.x * BN * ldb;
    C  += (size_t)blockIdx.z * sC + (size_t)blockIdx.y * BM * ldc
        + (size_t)blockIdx.x * BN;

    const int arow = tid >> 1, acol = (tid & 1) << 2;
    const int trow = (tid >> 4) * TM;
    const int tcol = (tid & 15) * TN;

    float acc[TM][TN];
#pragma unroll
    for (int i = 0; i < TM; i++)
#pragma unroll
        for (int j = 0; j < TN; j++) acc[i][j] = 0.f;

    for (int k0 = 0; k0 < K; k0 += BK) {
        float4 a = *(const float4*)(A + (size_t)arow * lda + k0 + acol);
        As[acol + 0][arow] = a.x;
        As[acol + 1][arow] = a.y;
        As[acol + 2][arow] = a.z;
        As[acol + 3][arow] = a.w;
        float4 b = *(const float4*)(Bm + (size_t)arow * ldb + k0 + acol);
        Bs[acol + 0][arow] = b.x;
        Bs[acol + 1][arow] = b.y;
        Bs[acol + 2][arow] = b.z;
        Bs[acol + 3][arow] = b.w;
        __syncthreads();
#pragma unroll
        for (int kk = 0; kk < BK; kk++) {
            float ra[TM], rb[TN];
            *(float4*)&ra[0] = *(const float4*)&As[kk][trow];
            *(float4*)&ra[4] = *(const float4*)&As[kk][trow + 4];
            *(float4*)&rb[0] = *(const float4*)&Bs[kk][tcol];
            *(float4*)&rb[4] = *(const float4*)&Bs[kk][tcol + 4];
#pragma unroll
            for (int i = 0; i < TM; i++)
#pragma unroll
                for (int j = 0; j < TN; j++)
                    acc[i][j] = fmaf(ra[i], rb[j], acc[i][j]);
        }
        __syncthreads();
    }

#pragma unroll
    for (int i = 0; i < TM; i++) {
        float o[TN];
#pragma unroll
        for (int j = 0; j < TN; j++) o[j] = acc[i][j] * scale;
        float* Cr = C + (size_t)(trow + i) * ldc + tcol;
        *(float4*)Cr       = *(float4*)&o[0];
        *(float4*)(Cr + 4) = *(float4*)&o[4];
    }
}

// ---------------------------------------------------------------------------
// Row softmax in place on g_S.  grid (4096, 1, B), 256 threads.
// ---------------------------------------------------------------------------
__global__ __launch_bounds__(256)
void softmax_rows(float* __restrict__ S)
{
    float* row = S + ((size_t)blockIdx.z * N_ + blockIdx.x) * N_;
    float4* row4 = (float4*)row;
    const int tid = threadIdx.x;
    const int lane = tid & 31, wid = tid >> 5;
    __shared__ float redm[8];
    __shared__ float reds[8];
    __shared__ float bval;

    float4 r[4];
    float mx = -1e30f;
#pragma unroll
    for (int k = 0; k < 4; k++) {
        r[k] = row4[tid + k * 256];
        mx = fmaxf(mx, fmaxf(fmaxf(r[k].x, r[k].y), fmaxf(r[k].z, r[k].w)));
    }
#pragma unroll
    for (int off = 16; off; off >>= 1)
        mx = fmaxf(mx, __shfl_xor_sync(0xffffffffu, mx, off));
    if (lane == 0) redm[wid] = mx;
    __syncthreads();
    if (tid == 0) {
        float m = redm[0];
#pragma unroll
        for (int i = 1; i < 8; i++) m = fmaxf(m, redm[i]);
        bval = m;
    }
    __syncthreads();
    mx = bval;

    float s = 0.f;
#pragma unroll
    for (int k = 0; k < 4; k++) {
        r[k].x = __expf(r[k].x - mx); s += r[k].x;
        r[k].y = __expf(r[k].y - mx); s += r[k].y;
        r[k].z = __expf(r[k].z - mx); s += r[k].z;
        r[k].w = __expf(r[k].w - mx); s += r[k].w;
    }
#pragma unroll
    for (int off = 16; off; off >>= 1)
        s += __shfl_xor_sync(0xffffffffu, s, off);
    if (lane == 0) reds[wid] = s;
    __syncthreads();
    if (tid == 0) {
        float t = 0.f;
#pragma unroll
        for (int i = 0; i < 8; i++) t += reds[i];
        bval = 1.f / t;
    }
    __syncthreads();
    const float inv = bval;
#pragma unroll
    for (int k = 0; k < 4; k++) {
        r[k].x *= inv; r[k].y *= inv; r[k].z *= inv; r[k].w *= inv;
        row4[tid + k * 256] = r[k];
    }
}

// ---------------------------------------------------------------------------
// Hyperedge branch
// ---------------------------------------------------------------------------
// grid (MAXE, B), 256 threads: per-edge degree + mean feature vector
__global__ __launch_bounds__(256)
void edge_mean_kernel(const float* __restrict__ x, const int* __restrict__ Hm)
{
    const int e = blockIdx.x, b = blockIdx.y, f = threadIdx.x;
    const float* xb = x + (size_t)b * N_ * F_;
    float sum = 0.f;
    int cnt = 0;
    for (int n = 0; n < N_; n++) {
        if (Hm[(size_t)n * E_ + e]) {
            sum += xb[(size_t)n * F_ + f];
            cnt++;
        }
    }
    const float deg = (float)cnt;
    g_mean[((size_t)b * MAXE + e) * F_ + f] = sum / fmaxf(deg, 1.0f);
    if (f == 0 && b == 0) g_deg[e] = deg;
}

// grid (MAXE, B), 128 threads: 256->128->64->1 MLP on mean features
__global__ __launch_bounds__(128)
void ctx_kernel(const float* __restrict__ m1w, const float* __restrict__ m1b,
                const float* __restrict__ m2w, const float* __restrict__ m2b,
                const float* __restrict__ m3w, const float* __restrict__ m3b)
{
    const int e = blockIdx.x, b = blockIdx.y, t = threadIdx.x;
    __shared__ float ms[F_];
    __shared__ float h1[H1_];
    __shared__ float h2[H2_];
    __shared__ float red[4];

    const float* mp = g_mean + ((size_t)b * MAXE + e) * F_;
    ms[t]       = mp[t];
    ms[t + 128] = mp[t + 128];
    __syncthreads();

    float s = m1b[t];
    for (int k = 0; k < F_; k++) s += ms[k] * m1w[k * H1_ + t];
    h1[t] = fmaxf(s, 0.f);
    __syncthreads();

    if (t < H2_) {
        float s2 = m2b[t];
        for (int k = 0; k < H1_; k++) s2 += h1[k] * m2w[k * H2_ + t];
        h2[t] = fmaxf(s2, 0.f);
    }
    __syncthreads();

    float p = (t < H2_) ? h2[t] * m3w[t] : 0.f;
#pragma unroll
    for (int off = 16; off; off >>= 1)
        p += __shfl_xor_sync(0xffffffffu, p, off);
    if ((t & 31) == 0) red[t >> 5] = p;
    __syncthreads();
    if (t == 0)
        g_ctx[b * MAXE + e] = red[0] + red[1] + red[2] + red[3] + m3b[0];
}

// grid (N, B), 256 threads: compat + adaptive weights -> out[..., 0:E]
__global__ __launch_bounds__(256)
void aw_kernel(const float* __restrict__ x, const int* __restrict__ Hm,
               const float* __restrict__ cw, const float* __restrict__ cb,
               const float* __restrict__ hb, const float* __restrict__ alpha,
               float* __restrict__ out)
{
    const int n = blockIdx.x, b = blockIdx.y, t = threadIdx.x;
    __shared__ float red[8];
    __shared__ float compat_s;

    float p = x[((size_t)b * N_ + n) * F_ + t] * cw[t];
#pragma unroll
    for (int off = 16; off; off >>= 1)
        p += __shfl_xor_sync(0xffffffffu, p, off);
    if ((t & 31) == 0) red[t >> 5] = p;
    __syncthreads();
    if (t == 0) {
        float s = 0.f;
#pragma unroll
        for (int i = 0; i < 8; i++) s += red[i];
        compat_s = s + cb[0] + hb[0];
    }
    __syncthreads();

    float val = 0.f;
    if (t < MAXE) {
        if (Hm[(size_t)n * E_ + t] && g_deg[t] > 1.0f) {
            float z = compat_s + alpha[0] * g_ctx[b * MAXE + t];
            val = 1.f / (1.f + __expf(-z));
        }
    }
    out[((size_t)b * N_ + n) * OUTC + t] = val;
}

// ---------------------------------------------------------------------------
// Launch
// ---------------------------------------------------------------------------
extern "C" void kernel_launch(void* const* d_in, const int* in_sizes, int n_in,
                              void* d_out, int out_size)
{
    const float* x      = (const float*)d_in[0];
    const int*   Hm     = (const int*)  d_in[1];
    const float* weight = (const float*)d_in[2];
    const float* bias   = (const float*)d_in[3];
    const float* Wn_w   = (const float*)d_in[4];
    const float* Wn_b   = (const float*)d_in[5];
    const float* m1_w   = (const float*)d_in[6];
    const float* m1_b   = (const float*)d_in[7];
    const float* m2_w   = (const float*)d_in[8];
    const float* m2_b   = (const float*)d_in[9];
    const float* m3_w   = (const float*)d_in[10];
    const float* m3_b   = (const float*)d_in[11];
    const float* c_w    = (const float*)d_in[12];
    const float* c_b    = (const float*)d_in[13];
    const float* hedgeb = (const float*)d_in[14];
    const float* alpha  = (const float*)d_in[15];
    float* out = (float*)d_out;

    float *xp, *v, *S;
    cudaGetSymbolAddress((void**)&xp, g_xp);
    cudaGetSymbolAddress((void**)&v,  g_v);
    cudaGetSymbolAddress((void**)&S,  g_S);

    // ---- hyperedge branch ----
    edge_mean_kernel<<<dim3(MAXE, B_), 256>>>(x, Hm);
    ctx_kernel<<<dim3(MAXE, B_), 128>>>(m1_w, m1_b, m2_w, m2_b, m3_w, m3_b);
    aw_kernel<<<dim3(N_, B_), 256>>>(x, Hm, c_w, c_b, hedgeb, alpha, out);

    // ---- projections: xp = x@Wn_w + Wn_b ; V = x@weight ----
    // treat x as [B*N, F]
    sgemm_nn<<<dim3(F_ / BN, (B_ * N_) / BM, 1), 256>>>(
        x, Wn_w, Wn_b, xp,
        B_ * N_, F_, F_, F_, F_, F_,
        (size_t)0, (size_t)0, (size_t)0, 1.0f);
    sgemm_nn<<<dim3(F_ / BN, (B_ * N_) / BM, 1), 256>>>(
        x, weight, nullptr, v,
        B_ * N_, F_, F_, F_, F_, F_,
        (size_t)0, (size_t)0, (size_t)0, 1.0f);

    // ---- S = xp @ xp^T / 16 (all batches via blockIdx.z) ----
    sgemm_nt<<<dim3(N_ / BN, N_ / BM, B_), 256>>>(
        xp, xp, S,
        N_, N_, F_, F_, F_, N_,
        (size_t)N_ * F_, (size_t)N_ * F_, (size_t)N_ * N_, 0.0625f);

    // ---- softmax rows ----
    softmax_rows<<<dim3(N_, 1, B_), 256>>>(S);

    // ---- y = softmax(S) @ V + bias -> out[..., E:E+F] ----
    sgemm_nn<<<dim3(F_ / BN, N_ / BM, B_), 256>>>(
        S, v, bias, out + E_,
        N_, F_, N_, N_, F_, OUTC,
        (size_t)N_ * N_, (size_t)N_ * F_, (size_t)N_ * OUTC, 1.0f);
}

// round 6
// speedup vs baseline: 2.2720x; 2.2720x over previous
#include <cuda_runtime.h>
#include <cuda_bf16.h>
#include <cstdint>
#include <cstddef>

// Problem constants
#define B_   4
#define N_   4096
#define E_   256
#define F_   256
#define MAXE 50
#define H1_  128
#define H2_  64
#define OUTC 512

// ---------------------------------------------------------------------------
// Static device scratch
// ---------------------------------------------------------------------------
__device__ float g_xp[B_ * N_ * F_];                 // xp fp32 (16 MB)
__device__ float g_v [B_ * N_ * F_];                 // v  fp32 (16 MB)
__device__ float g_S [67108864];                     // scores fp32 (256 MB)
__device__ __nv_bfloat16 g_xh [B_ * N_ * F_];        // x hi
__device__ __nv_bfloat16 g_xl [B_ * N_ * F_];        // x lo
__device__ __nv_bfloat16 g_xph[B_ * N_ * F_];        // xp hi
__device__ __nv_bfloat16 g_xpl[B_ * N_ * F_];
__device__ __nv_bfloat16 g_vth[B_ * F_ * N_];        // v^T hi  [b][256][4096]
__device__ __nv_bfloat16 g_vtl[B_ * F_ * N_];
__device__ __nv_bfloat16 g_Ph [67108864];            // softmax(S) hi (128 MB)
__device__ __nv_bfloat16 g_Pl [67108864];            // softmax(S) lo (128 MB)
__device__ __nv_bfloat16 g_wth [F_ * F_], g_wtl [F_ * F_];   // weight^T hi/lo
__device__ __nv_bfloat16 g_wnth[F_ * F_], g_wntl[F_ * F_];   // Wn_w^T hi/lo
__device__ float g_mean[B_ * MAXE * F_];
__device__ float g_ctx [B_ * MAXE];
__device__ float g_deg [MAXE];

// ---------------------------------------------------------------------------
// PTX helpers (base sm_100-safe: mma.sync / ldmatrix / cp.async)
// ---------------------------------------------------------------------------
__device__ __forceinline__ uint32_t smem_u32(const void* p) {
    uint32_t a;
    asm("{ .reg .u64 t; cvta.to.shared.u64 t, %1; cvt.u32.u64 %0, t; }"
        : "=r"(a) : "l"(p));
    return a;
}
__device__ __forceinline__ void cp_async16(uint32_t s, const void* g) {
    asm volatile("cp.async.cg.shared.global [%0], [%1], 16;\n"
        :: "r"(s), "l"((unsigned long long)__cvta_generic_to_global(g)) : "memory");
}
__device__ __forceinline__ void cp_commit() {
    asm volatile("cp.async.commit_group;\n" ::: "memory");
}
__device__ __forceinline__ void cp_wait0() {
    asm volatile("cp.async.wait_group 0;\n" ::: "memory");
}
__device__ __forceinline__ void ldmatrix_x4(uint32_t* r, uint32_t addr) {
    asm volatile("ldmatrix.sync.aligned.m8n8.x4.shared.b16 {%0,%1,%2,%3}, [%4];\n"
        : "=r"(r[0]), "=r"(r[1]), "=r"(r[2]), "=r"(r[3]) : "r"(addr));
}
__device__ __forceinline__ void mma_bf16(float* d, const uint32_t* a,
                                         uint32_t b0, uint32_t b1) {
    asm volatile(
        "mma.sync.aligned.m16n8k16.row.col.f32.bf16.bf16.f32 "
        "{%0,%1,%2,%3}, {%4,%5,%6,%7}, {%8,%9}, {%0,%1,%2,%3};\n"
        : "+f"(d[0]), "+f"(d[1]), "+f"(d[2]), "+f"(d[3])
        : "r"(a[0]), "r"(a[1]), "r"(a[2]), "r"(a[3]), "r"(b0), "r"(b1));
}

// ---------------------------------------------------------------------------
// bf16x3-split GEMM via mma.sync: D[m][n] = scale*sum_k A[m,k]*B[n,k] (+bias)
// Computes AhBh + AlBh + AhBl as 3 K-passes of one pipelined tile loop.
// CTA tile 128x128, K-chunk 64, 256 threads (8 warps as 2m x 4n, warp 64x32).
// Smem: 2 stages x (A 16KB + B 16KB) = 64KB, XOR-swizzled for ldmatrix.
// ---------------------------------------------------------------------------
#define GEMM_SMEM 65536

__global__ __launch_bounds__(256)
void gemm_bf16x3(const __nv_bfloat16* __restrict__ Ah, const __nv_bfloat16* __restrict__ Al,
                 const __nv_bfloat16* __restrict__ Bh, const __nv_bfloat16* __restrict__ Bl,
                 float* __restrict__ C, const float* __restrict__ bias,
                 int K, int ldc,
                 long long sA, long long sB, long long sC, float scale)
{
    extern __shared__ __align__(16) char smem[];
    const uint32_t sbase = smem_u32(smem);
    const int tid = threadIdx.x;
    const int lane = tid & 31;
    const int wid = tid >> 5;
    const int wm = wid & 1;        // 2 warp rows  (64 rows each)
    const int wn = wid >> 1;       // 4 warp cols  (32 cols each)

    const size_t Ms = (size_t)blockIdx.y * 128;
    const size_t Ns = (size_t)blockIdx.x * 128;
    const int z = blockIdx.z;
    const __nv_bfloat16* pAh = Ah + (size_t)z * sA + Ms * K;
    const __nv_bfloat16* pAl = Al + (size_t)z * sA + Ms * K;
    const __nv_bfloat16* pBh = Bh + (size_t)z * sB + Ns * K;
    const __nv_bfloat16* pBl = Bl + (size_t)z * sB + Ns * K;
    float* pC = C + (size_t)z * sC + Ms * ldc + Ns;

    const int KC = K >> 6;          // 64-wide K chunks per pass
    const int T = 3 * KC;           // 3 split passes

    float acc[4][4][4];
#pragma unroll
    for (int i = 0; i < 4; i++)
#pragma unroll
        for (int j = 0; j < 4; j++)
#pragma unroll
            for (int k = 0; k < 4; k++) acc[i][j][k] = 0.f;

    // issue cp.async for chunk t into stage t&1
    auto load_chunk = [&](int t) {
        const int pass = t / KC;
        const int kk = (t - pass * KC) << 6;
        const __nv_bfloat16* pA = (pass == 1) ? pAl : pAh;
        const __nv_bfloat16* pB = (pass == 2) ? pBl : pBh;
        const uint32_t st = sbase + (t & 1) * 32768;
#pragma unroll
        for (int i = 0; i < 4; i++) {
            int idx = i * 256 + tid;
            int row = idx >> 3, c = idx & 7;
            uint32_t sa = st + row * 128 + ((c ^ (row & 7)) << 4);
            cp_async16(sa, pA + (size_t)row * K + kk + c * 8);
        }
#pragma unroll
        for (int i = 0; i < 4; i++) {
            int idx = i * 256 + tid;
            int row = idx >> 3, c = idx & 7;
            uint32_t sa = st + 16384 + row * 128 + ((c ^ (row & 7)) << 4);
            cp_async16(sa, pB + (size_t)row * K + kk + c * 8);
        }
        cp_commit();
    };

    load_chunk(0);

#pragma unroll 1
    for (int t = 0; t < T; t++) {
        cp_wait0();
        __syncthreads();
        if (t + 1 < T) load_chunk(t + 1);

        const uint32_t Ab = sbase + (t & 1) * 32768;
        const uint32_t Bb = Ab + 16384;
#pragma unroll
        for (int ks = 0; ks < 4; ks++) {
            uint32_t afr[4][4];
#pragma unroll
            for (int mt = 0; mt < 4; mt++) {
                int arow = wm * 64 + mt * 16 + (lane & 15);
                int c = ks * 2 + (lane >> 4);
                ldmatrix_x4(afr[mt], Ab + arow * 128 + ((c ^ (arow & 7)) << 4));
            }
            uint32_t bfr[2][4];
#pragma unroll
            for (int np = 0; np < 2; np++) {
                int nrow = wn * 32 + np * 16 + (lane & 7) + ((lane >> 4) << 3);
                int c = ks * 2 + ((lane >> 3) & 1);
                ldmatrix_x4(bfr[np], Bb + nrow * 128 + ((c ^ (nrow & 7)) << 4));
            }
#pragma unroll
            for (int mt = 0; mt < 4; mt++)
#pragma unroll
                for (int nt = 0; nt < 4; nt++)
                    mma_bf16(acc[mt][nt], afr[mt],
                             bfr[nt >> 1][(nt & 1) * 2],
                             bfr[nt >> 1][(nt & 1) * 2 + 1]);
        }
    }

    // epilogue: direct float2 stores
    const int tg = lane >> 2, tq = lane & 3;
#pragma unroll
    for (int mt = 0; mt < 4; mt++) {
#pragma unroll
        for (int nt = 0; nt < 4; nt++) {
            int r0 = wm * 64 + mt * 16 + tg;
            int cc = wn * 32 + nt * 8 + tq * 2;
            float b0 = 0.f, b1 = 0.f;
            if (bias) { b0 = bias[Ns + cc]; b1 = bias[Ns + cc + 1]; }
            float2 v0 = { acc[mt][nt][0] * scale + b0, acc[mt][nt][1] * scale + b1 };
            float2 v1 = { acc[mt][nt][2] * scale + b0, acc[mt][nt][3] * scale + b1 };
            *(float2*)(pC + (size_t)r0 * ldc + cc)       = v0;
            *(float2*)(pC + (size_t)(r0 + 8) * ldc + cc) = v1;
        }
    }
}

// ---------------------------------------------------------------------------
// fp32 -> (bf16 hi, bf16 lo) split, 4 elements/thread
// ---------------------------------------------------------------------------
__global__ __launch_bounds__(256)
void conv_split(const float* __restrict__ in, __nv_bfloat16* __restrict__ hi,
                __nv_bfloat16* __restrict__ lo, int n)
{
    int i = (blockIdx.x * 256 + threadIdx.x) * 4;
    if (i >= n) return;
    float4 v = *(const float4*)(in + i);
    __nv_bfloat16 h0 = __float2bfloat16(v.x), h1 = __float2bfloat16(v.y);
    __nv_bfloat16 h2 = __float2bfloat16(v.z), h3 = __float2bfloat16(v.w);
    __nv_bfloat162 ph0(h0, h1), ph1(h2, h3);
    __nv_bfloat162 pl0(__float2bfloat16(v.x - __bfloat162float(h0)),
                       __float2bfloat16(v.y - __bfloat162float(h1)));
    __nv_bfloat162 pl1(__float2bfloat16(v.z - __bfloat162float(h2)),
                       __float2bfloat16(v.w - __bfloat162float(h3)));
    *(__nv_bfloat162*)(hi + i)     = ph0;
    *(__nv_bfloat162*)(hi + i + 2) = ph1;
    *(__nv_bfloat162*)(lo + i)     = pl0;
    *(__nv_bfloat162*)(lo + i + 2) = pl1;
}

// ---------------------------------------------------------------------------
// transpose + split: in [R][C] fp32 -> out [C][R] bf16 hi/lo. block (32,8)
// ---------------------------------------------------------------------------
__global__ __launch_bounds__(256)
void transpose_split(const float* __restrict__ in, __nv_bfloat16* __restrict__ oh,
                     __nv_bfloat16* __restrict__ ol, int R, int C,
                     long long sIn, long long sOut)
{
    __shared__ float tile[32][33];
    const int c0 = blockIdx.x * 32, r0 = blockIdx.y * 32, z = blockIdx.z;
    in += (size_t)z * sIn; oh += (size_t)z * sOut; ol += (size_t)z * sOut;
    const int tx = threadIdx.x, ty = threadIdx.y;
#pragma unroll
    for (int j = 0; j < 4; j++)
        tile[ty + 8 * j][tx] = in[(size_t)(r0 + ty + 8 * j) * C + c0 + tx];
    __syncthreads();
#pragma unroll
    for (int j = 0; j < 4; j++) {
        float v = tile[tx][ty + 8 * j];
        __nv_bfloat16 h = __float2bfloat16(v);
        size_t o = (size_t)(c0 + ty + 8 * j) * R + r0 + tx;
        oh[o] = h;
        ol[o] = __float2bfloat16(v - __bfloat162float(h));
    }
}

// ---------------------------------------------------------------------------
// Row softmax on g_S -> bf16 hi/lo P.  grid (4096, 1, B), 256 threads.
// ---------------------------------------------------------------------------
__global__ __launch_bounds__(256)
void softmax_split(const float* __restrict__ S, __nv_bfloat16* __restrict__ Ph,
                   __nv_bfloat16* __restrict__ Pl)
{
    const size_t row = (size_t)blockIdx.z * N_ + blockIdx.x;
    const float4* row4 = (const float4*)(S + row * N_);
    __nv_bfloat162* ph2 = (__nv_bfloat162*)(Ph + row * N_);
    __nv_bfloat162* pl2 = (__nv_bfloat162*)(Pl + row * N_);
    const int tid = threadIdx.x, lane = tid & 31, wid = tid >> 5;
    __shared__ float red[8];
    __shared__ float bval;

    float4 r[4];
    float mx = -1e30f;
#pragma unroll
    for (int k = 0; k < 4; k++) {
        r[k] = row4[tid + k * 256];
        mx = fmaxf(mx, fmaxf(fmaxf(r[k].x, r[k].y), fmaxf(r[k].z, r[k].w)));
    }
#pragma unroll
    for (int off = 16; off; off >>= 1)
        mx = fmaxf(mx, __shfl_xor_sync(0xffffffffu, mx, off));
    if (lane == 0) red[wid] = mx;
    __syncthreads();
    if (tid == 0) {
        float m = red[0];
#pragma unroll
        for (int i = 1; i < 8; i++) m = fmaxf(m, red[i]);
        bval = m;
    }
    __syncthreads();
    mx = bval;

    float s = 0.f;
#pragma unroll
    for (int k = 0; k < 4; k++) {
        r[k].x = __expf(r[k].x - mx); s += r[k].x;
        r[k].y = __expf(r[k].y - mx); s += r[k].y;
        r[k].z = __expf(r[k].z - mx); s += r[k].z;
        r[k].w = __expf(r[k].w - mx); s += r[k].w;
    }
#pragma unroll
    for (int off = 16; off; off >>= 1)
        s += __shfl_xor_sync(0xffffffffu, s, off);
    if (lane == 0) red[wid] = s;
    __syncthreads();
    if (tid == 0) {
        float t = 0.f;
#pragma unroll
        for (int i = 0; i < 8; i++) t += red[i];
        bval = 1.f / t;
    }
    __syncthreads();
    const float inv = bval;
#pragma unroll
    for (int k = 0; k < 4; k++) {
        float a = r[k].x * inv, b = r[k].y * inv, c = r[k].z * inv, d = r[k].w * inv;
        __nv_bfloat16 ha = __float2bfloat16(a), hb = __float2bfloat16(b);
        __nv_bfloat16 hc = __float2bfloat16(c), hd = __float2bfloat16(d);
        int idx = (tid + k * 256) * 2;
        ph2[idx]     = __nv_bfloat162(ha, hb);
        ph2[idx + 1] = __nv_bfloat162(hc, hd);
        pl2[idx]     = __nv_bfloat162(__float2bfloat16(a - __bfloat162float(ha)),
                                      __float2bfloat16(b - __bfloat162float(hb)));
        pl2[idx + 1] = __nv_bfloat162(__float2bfloat16(c - __bfloat162float(hc)),
                                      __float2bfloat16(d - __bfloat162float(hd)));
    }
}

// ---------------------------------------------------------------------------
// Hyperedge branch
// ---------------------------------------------------------------------------
__global__ __launch_bounds__(256)
void edge_mean_kernel(const float* __restrict__ x, const int* __restrict__ Hm)
{
    const int e = blockIdx.x, b = blockIdx.y, f = threadIdx.x;
    const float* xb = x + (size_t)b * N_ * F_;
    float sum = 0.f;
    int cnt = 0;
    for (int n = 0; n < N_; n++) {
        if (Hm[(size_t)n * E_ + e]) {
            sum += xb[(size_t)n * F_ + f];
            cnt++;
        }
    }
    const float deg = (float)cnt;
    g_mean[((size_t)b * MAXE + e) * F_ + f] = sum / fmaxf(deg, 1.0f);
    if (f == 0 && b == 0) g_deg[e] = deg;
}

__global__ __launch_bounds__(128)
void ctx_kernel(const float* __restrict__ m1w, const float* __restrict__ m1b,
                const float* __restrict__ m2w, const float* __restrict__ m2b,
                const float* __restrict__ m3w, const float* __restrict__ m3b)
{
    const int e = blockIdx.x, b = blockIdx.y, t = threadIdx.x;
    __shared__ float ms[F_];
    __shared__ float h1[H1_];
    __shared__ float h2[H2_];
    __shared__ float red[4];

    const float* mp = g_mean + ((size_t)b * MAXE + e) * F_;
    ms[t]       = mp[t];
    ms[t + 128] = mp[t + 128];
    __syncthreads();

    float s = m1b[t];
    for (int k = 0; k < F_; k++) s += ms[k] * m1w[k * H1_ + t];
    h1[t] = fmaxf(s, 0.f);
    __syncthreads();

    if (t < H2_) {
        float s2 = m2b[t];
        for (int k = 0; k < H1_; k++) s2 += h1[k] * m2w[k * H2_ + t];
        h2[t] = fmaxf(s2, 0.f);
    }
    __syncthreads();

    float p = (t < H2_) ? h2[t] * m3w[t] : 0.f;
#pragma unroll
    for (int off = 16; off; off >>= 1)
        p += __shfl_xor_sync(0xffffffffu, p, off);
    if ((t & 31) == 0) red[t >> 5] = p;
    __syncthreads();
    if (t == 0)
        g_ctx[b * MAXE + e] = red[0] + red[1] + red[2] + red[3] + m3b[0];
}

__global__ __launch_bounds__(256)
void aw_kernel(const float* __restrict__ x, const int* __restrict__ Hm,
               const float* __restrict__ cw, const float* __restrict__ cb,
               const float* __restrict__ hb, const float* __restrict__ alpha,
               float* __restrict__ out)
{
    const int n = blockIdx.x, b = blockIdx.y, t = threadIdx.x;
    __shared__ float red[8];
    __shared__ float compat_s;

    float p = x[((size_t)b * N_ + n) * F_ + t] * cw[t];
#pragma unroll
    for (int off = 16; off; off >>= 1)
        p += __shfl_xor_sync(0xffffffffu, p, off);
    if ((t & 31) == 0) red[t >> 5] = p;
    __syncthreads();
    if (t == 0) {
        float s = 0.f;
#pragma unroll
        for (int i = 0; i < 8; i++) s += red[i];
        compat_s = s + cb[0] + hb[0];
    }
    __syncthreads();

    float val = 0.f;
    if (t < MAXE) {
        if (Hm[(size_t)n * E_ + t] && g_deg[t] > 1.0f) {
            float z = compat_s + alpha[0] * g_ctx[b * MAXE + t];
            val = 1.f / (1.f + __expf(-z));
        }
    }
    out[((size_t)b * N_ + n) * OUTC + t] = val;
}

// ---------------------------------------------------------------------------
// Launch
// ---------------------------------------------------------------------------
extern "C" void kernel_launch(void* const* d_in, const int* in_sizes, int n_in,
                              void* d_out, int out_size)
{
    const float* x      = (const float*)d_in[0];
    const int*   Hm     = (const int*)  d_in[1];
    const float* weight = (const float*)d_in[2];
    const float* bias   = (const float*)d_in[3];
    const float* Wn_w   = (const float*)d_in[4];
    const float* Wn_b   = (const float*)d_in[5];
    const float* m1_w   = (const float*)d_in[6];
    const float* m1_b   = (const float*)d_in[7];
    const float* m2_w   = (const float*)d_in[8];
    const float* m2_b   = (const float*)d_in[9];
    const float* m3_w   = (const float*)d_in[10];
    const float* m3_b   = (const float*)d_in[11];
    const float* c_w    = (const float*)d_in[12];
    const float* c_b    = (const float*)d_in[13];
    const float* hedgeb = (const float*)d_in[14];
    const float* alpha  = (const float*)d_in[15];
    float* out = (float*)d_out;

    float *xp, *v, *S;
    __nv_bfloat16 *xh, *xl, *xph, *xpl, *vth, *vtl, *Ph, *Pl;
    __nv_bfloat16 *wth, *wtl, *wnth, *wntl;
    cudaGetSymbolAddress((void**)&xp,  g_xp);
    cudaGetSymbolAddress((void**)&v,   g_v);
    cudaGetSymbolAddress((void**)&S,   g_S);
    cudaGetSymbolAddress((void**)&xh,  g_xh);
    cudaGetSymbolAddress((void**)&xl,  g_xl);
    cudaGetSymbolAddress((void**)&xph, g_xph);
    cudaGetSymbolAddress((void**)&xpl, g_xpl);
    cudaGetSymbolAddress((void**)&vth, g_vth);
    cudaGetSymbolAddress((void**)&vtl, g_vtl);
    cudaGetSymbolAddress((void**)&Ph,  g_Ph);
    cudaGetSymbolAddress((void**)&Pl,  g_Pl);
    cudaGetSymbolAddress((void**)&wth, g_wth);
    cudaGetSymbolAddress((void**)&wtl, g_wtl);
    cudaGetSymbolAddress((void**)&wnth, g_wnth);
    cudaGetSymbolAddress((void**)&wntl, g_wntl);

    cudaFuncSetAttribute(gemm_bf16x3,
                         cudaFuncAttributeMaxDynamicSharedMemorySize, GEMM_SMEM);

    const int nx = B_ * N_ * F_;   // 4M elements

    // hyperedge branch (independent)
    edge_mean_kernel<<<dim3(MAXE, B_), 256>>>(x, Hm);
    ctx_kernel<<<dim3(MAXE, B_), 128>>>(m1_w, m1_b, m2_w, m2_b, m3_w, m3_b);
    aw_kernel<<<dim3(N_, B_), 256>>>(x, Hm, c_w, c_b, hedgeb, alpha, out);

    // input conversions
    conv_split<<<nx / 4 / 256, 256>>>(x, xh, xl, nx);
    transpose_split<<<dim3(8, 8, 1), dim3(32, 8)>>>(weight, wth, wtl, F_, F_, 0, 0);
    transpose_split<<<dim3(8, 8, 1), dim3(32, 8)>>>(Wn_w, wnth, wntl, F_, F_, 0, 0);

    // projections: xp = x@Wn_w + Wn_b ; v = x@weight   (M = B*N merged)
    gemm_bf16x3<<<dim3(F_ / 128, (B_ * N_) / 128, 1), 256, GEMM_SMEM>>>(
        xh, xl, wnth, wntl, xp, Wn_b, F_, F_, 0, 0, 0, 1.0f);
    gemm_bf16x3<<<dim3(F_ / 128, (B_ * N_) / 128, 1), 256, GEMM_SMEM>>>(
        xh, xl, wth, wtl, v, nullptr, F_, F_, 0, 0, 0, 1.0f);

    // splits of xp ; v transposed per batch
    conv_split<<<nx / 4 / 256, 256>>>(xp, xph, xpl, nx);
    transpose_split<<<dim3(F_ / 32, N_ / 32, B_), dim3(32, 8)>>>(
        v, vth, vtl, N_, F_, (long long)N_ * F_, (long long)F_ * N_);

    // S = xp @ xp^T / 16
    gemm_bf16x3<<<dim3(N_ / 128, N_ / 128, B_), 256, GEMM_SMEM>>>(
        xph, xpl, xph, xpl, S, nullptr, F_, N_,
        (long long)N_ * F_, (long long)N_ * F_, (long long)N_ * N_, 0.0625f);

    // P = softmax(S) -> bf16 hi/lo
    softmax_split<<<dim3(N_, 1, B_), 256>>>(S, Ph, Pl);

    // y = P @ V + bias -> out[..., E:E+F]
    gemm_bf16x3<<<dim3(F_ / 128, N_ / 128, B_), 256, GEMM_SMEM>>>(
        Ph, Pl, vth, vtl, out + E_, bias, N_, OUTC,
        (long long)N_ * N_, (long long)F_ * N_, (long long)N_ * OUTC, 1.0f);
}

// round 7
// speedup vs baseline: 2.4968x; 1.0989x over previous
#include <cuda_runtime.h>
#include <cuda_bf16.h>
#include <cstdint>
#include <cstddef>

// Problem constants
#define B_   4
#define N_   4096
#define E_   256
#define F_   256
#define MAXE 50
#define H1_  128
#define H2_  64
#define OUTC 512

// ---------------------------------------------------------------------------
// Static device scratch
// ---------------------------------------------------------------------------
__device__ float g_v [B_ * N_ * F_];                 // v fp32 (16 MB)
__device__ __nv_bfloat16 g_Sb[67108864];             // scores bf16 (128 MB)
__device__ __nv_bfloat16 g_xh [B_ * N_ * F_];        // x hi
__device__ __nv_bfloat16 g_xl [B_ * N_ * F_];        // x lo
__device__ __nv_bfloat16 g_xph[B_ * N_ * F_];        // xp hi
__device__ __nv_bfloat16 g_xpl[B_ * N_ * F_];
__device__ __nv_bfloat16 g_vth[B_ * F_ * N_];        // v^T hi  [b][256][4096]
__device__ __nv_bfloat16 g_vtl[B_ * F_ * N_];
__device__ __nv_bfloat16 g_Ph [67108864];            // softmax(S) hi (128 MB)
__device__ __nv_bfloat16 g_Pl [67108864];            // softmax(S) lo (128 MB)
__device__ __nv_bfloat16 g_wth [F_ * F_], g_wtl [F_ * F_];   // weight^T hi/lo
__device__ __nv_bfloat16 g_wnth[F_ * F_], g_wntl[F_ * F_];   // Wn_w^T hi/lo
__device__ float g_mean[B_ * MAXE * F_];
__device__ float g_ctx [B_ * MAXE];
__device__ float g_deg [MAXE];

// ---------------------------------------------------------------------------
// PTX helpers (base sm_100-safe: mma.sync / ldmatrix / cp.async)
// ---------------------------------------------------------------------------
__device__ __forceinline__ uint32_t smem_u32(const void* p) {
    uint32_t a;
    asm("{ .reg .u64 t; cvta.to.shared.u64 t, %1; cvt.u32.u64 %0, t; }"
        : "=r"(a) : "l"(p));
    return a;
}
__device__ __forceinline__ void cp_async16(uint32_t s, const void* g) {
    asm volatile("cp.async.cg.shared.global [%0], [%1], 16;\n"
        :: "r"(s), "l"((unsigned long long)__cvta_generic_to_global(g)) : "memory");
}
__device__ __forceinline__ void cp_commit() {
    asm volatile("cp.async.commit_group;\n" ::: "memory");
}
__device__ __forceinline__ void cp_wait0() {
    asm volatile("cp.async.wait_group 0;\n" ::: "memory");
}
__device__ __forceinline__ void ldmatrix_x4(uint32_t* r, uint32_t addr) {
    asm volatile("ldmatrix.sync.aligned.m8n8.x4.shared.b16 {%0,%1,%2,%3}, [%4];\n"
        : "=r"(r[0]), "=r"(r[1]), "=r"(r[2]), "=r"(r[3]) : "r"(addr));
}
__device__ __forceinline__ void mma_bf16(float* d, const uint32_t* a,
                                         uint32_t b0, uint32_t b1) {
    asm volatile(
        "mma.sync.aligned.m16n8k16.row.col.f32.bf16.bf16.f32 "
        "{%0,%1,%2,%3}, {%4,%5,%6,%7}, {%8,%9}, {%0,%1,%2,%3};\n"
        : "+f"(d[0]), "+f"(d[1]), "+f"(d[2]), "+f"(d[3])
        : "r"(a[0]), "r"(a[1]), "r"(a[2]), "r"(a[3]), "r"(b0), "r"(b1));
}

// ---------------------------------------------------------------------------
// bf16 split GEMM via mma.sync: D[m][n] = scale*sum_k A[m,k]*B[n,k] (+bias)
// NPASS=3: AhBh + AlBh + AhBl.  NPASS=2: AhBh + AlBh.
// OMODE=0: fp32 out (C0). OMODE=1: bf16 out (C0). OMODE=2: bf16 hi/lo (C0,C1).
// CTA tile 128x128, K-chunk 64, 256 threads (8 warps as 2m x 4n, warp 64x32).
// Smem: 2 stages x (A 16KB + B 16KB) = 64KB, XOR-swizzled for ldmatrix.
// ---------------------------------------------------------------------------
#define GEMM_SMEM 65536

template <int NPASS, int OMODE>
__global__ __launch_bounds__(256)
void gemm_bf16s(const __nv_bfloat16* __restrict__ Ah, const __nv_bfloat16* __restrict__ Al,
                const __nv_bfloat16* __restrict__ Bh, const __nv_bfloat16* __restrict__ Bl,
                void* __restrict__ C0p, void* __restrict__ C1p,
                const float* __restrict__ bias, int K, int ldc,
                long long sA, long long sB, long long sC, float scale)
{
    extern __shared__ __align__(16) char smem[];
    const uint32_t sbase = smem_u32(smem);
    const int tid = threadIdx.x;
    const int lane = tid & 31;
    const int wid = tid >> 5;
    const int wm = wid & 1;        // 2 warp rows  (64 rows each)
    const int wn = wid >> 1;       // 4 warp cols  (32 cols each)

    const size_t Ms = (size_t)blockIdx.y * 128;
    const size_t Ns = (size_t)blockIdx.x * 128;
    const int z = blockIdx.z;
    const __nv_bfloat16* pAh = Ah + (size_t)z * sA + Ms * K;
    const __nv_bfloat16* pAl = Al + (size_t)z * sA + Ms * K;
    const __nv_bfloat16* pBh = Bh + (size_t)z * sB + Ns * K;
    const __nv_bfloat16* pBl = Bl + (size_t)z * sB + Ns * K;

    const int KC = K >> 6;          // 64-wide K chunks per pass
    const int T = NPASS * KC;

    float acc[4][4][4];
#pragma unroll
    for (int i = 0; i < 4; i++)
#pragma unroll
        for (int j = 0; j < 4; j++)
#pragma unroll
            for (int k = 0; k < 4; k++) acc[i][j][k] = 0.f;

    auto load_chunk = [&](int t) {
        const int pass = t / KC;
        const int kk = (t - pass * KC) << 6;
        const __nv_bfloat16* pA = (pass == 1) ? pAl : pAh;
        const __nv_bfloat16* pB = (pass == 2) ? pBl : pBh;
        const uint32_t st = sbase + (t & 1) * 32768;
#pragma unroll
        for (int i = 0; i < 4; i++) {
            int idx = i * 256 + tid;
            int row = idx >> 3, c = idx & 7;
            uint32_t sa = st + row * 128 + ((c ^ (row & 7)) << 4);
            cp_async16(sa, pA + (size_t)row * K + kk + c * 8);
        }
#pragma unroll
        for (int i = 0; i < 4; i++) {
            int idx = i * 256 + tid;
            int row = idx >> 3, c = idx & 7;
            uint32_t sa = st + 16384 + row * 128 + ((c ^ (row & 7)) << 4);
            cp_async16(sa, pB + (size_t)row * K + kk + c * 8);
        }
        cp_commit();
    };

    load_chunk(0);

#pragma unroll 1
    for (int t = 0; t < T; t++) {
        cp_wait0();
        __syncthreads();
        if (t + 1 < T) load_chunk(t + 1);

        const uint32_t Ab = sbase + (t & 1) * 32768;
        const uint32_t Bb = Ab + 16384;
#pragma unroll
        for (int ks = 0; ks < 4; ks++) {
            uint32_t afr[4][4];
#pragma unroll
            for (int mt = 0; mt < 4; mt++) {
                int arow = wm * 64 + mt * 16 + (lane & 15);
                int c = ks * 2 + (lane >> 4);
                ldmatrix_x4(afr[mt], Ab + arow * 128 + ((c ^ (arow & 7)) << 4));
            }
            uint32_t bfr[2][4];
#pragma unroll
            for (int np = 0; np < 2; np++) {
                int nrow = wn * 32 + np * 16 + (lane & 7) + ((lane >> 4) << 3);
                int c = ks * 2 + ((lane >> 3) & 1);
                ldmatrix_x4(bfr[np], Bb + nrow * 128 + ((c ^ (nrow & 7)) << 4));
            }
#pragma unroll
            for (int mt = 0; mt < 4; mt++)
#pragma unroll
                for (int nt = 0; nt < 4; nt++)
                    mma_bf16(acc[mt][nt], afr[mt],
                             bfr[nt >> 1][(nt & 1) * 2],
                             bfr[nt >> 1][(nt & 1) * 2 + 1]);
        }
    }

    // epilogue
    const int tg = lane >> 2, tq = lane & 3;
#pragma unroll
    for (int mt = 0; mt < 4; mt++) {
#pragma unroll
        for (int nt = 0; nt < 4; nt++) {
            int r0 = wm * 64 + mt * 16 + tg;
            int cc = wn * 32 + nt * 8 + tq * 2;
            float b0 = 0.f, b1 = 0.f;
            if (bias) { b0 = bias[Ns + cc]; b1 = bias[Ns + cc + 1]; }
            float v00 = acc[mt][nt][0] * scale + b0;
            float v01 = acc[mt][nt][1] * scale + b1;
            float v10 = acc[mt][nt][2] * scale + b0;
            float v11 = acc[mt][nt][3] * scale + b1;
            if (OMODE == 0) {
                float* pC = (float*)C0p + (size_t)z * sC + Ms * ldc + Ns;
                float2 w0 = { v00, v01 }, w1 = { v10, v11 };
                *(float2*)(pC + (size_t)r0 * ldc + cc)       = w0;
                *(float2*)(pC + (size_t)(r0 + 8) * ldc + cc) = w1;
            } else if (OMODE == 1) {
                __nv_bfloat16* pC = (__nv_bfloat16*)C0p + (size_t)z * sC + Ms * ldc + Ns;
                *(__nv_bfloat162*)(pC + (size_t)r0 * ldc + cc) =
                    __nv_bfloat162(__float2bfloat16(v00), __float2bfloat16(v01));
                *(__nv_bfloat162*)(pC + (size_t)(r0 + 8) * ldc + cc) =
                    __nv_bfloat162(__float2bfloat16(v10), __float2bfloat16(v11));
            } else {
                __nv_bfloat16* pH = (__nv_bfloat16*)C0p + (size_t)z * sC + Ms * ldc + Ns;
                __nv_bfloat16* pL = (__nv_bfloat16*)C1p + (size_t)z * sC + Ms * ldc + Ns;
                __nv_bfloat16 h00 = __float2bfloat16(v00), h01 = __float2bfloat16(v01);
                __nv_bfloat16 h10 = __float2bfloat16(v10), h11 = __float2bfloat16(v11);
                *(__nv_bfloat162*)(pH + (size_t)r0 * ldc + cc) = __nv_bfloat162(h00, h01);
                *(__nv_bfloat162*)(pH + (size_t)(r0 + 8) * ldc + cc) = __nv_bfloat162(h10, h11);
                *(__nv_bfloat162*)(pL + (size_t)r0 * ldc + cc) =
                    __nv_bfloat162(__float2bfloat16(v00 - __bfloat162float(h00)),
                                   __float2bfloat16(v01 - __bfloat162float(h01)));
                *(__nv_bfloat162*)(pL + (size_t)(r0 + 8) * ldc + cc) =
                    __nv_bfloat162(__float2bfloat16(v10 - __bfloat162float(h10)),
                                   __float2bfloat16(v11 - __bfloat162float(h11)));
            }
        }
    }
}

// ---------------------------------------------------------------------------
// fp32 -> (bf16 hi, bf16 lo) split, 4 elements/thread
// ---------------------------------------------------------------------------
__global__ __launch_bounds__(256)
void conv_split(const float* __restrict__ in, __nv_bfloat16* __restrict__ hi,
                __nv_bfloat16* __restrict__ lo, int n)
{
    int i = (blockIdx.x * 256 + threadIdx.x) * 4;
    if (i >= n) return;
    float4 v = *(const float4*)(in + i);
    __nv_bfloat16 h0 = __float2bfloat16(v.x), h1 = __float2bfloat16(v.y);
    __nv_bfloat16 h2 = __float2bfloat16(v.z), h3 = __float2bfloat16(v.w);
    __nv_bfloat162 ph0(h0, h1), ph1(h2, h3);
    __nv_bfloat162 pl0(__float2bfloat16(v.x - __bfloat162float(h0)),
                       __float2bfloat16(v.y - __bfloat162float(h1)));
    __nv_bfloat162 pl1(__float2bfloat16(v.z - __bfloat162float(h2)),
                       __float2bfloat16(v.w - __bfloat162float(h3)));
    *(__nv_bfloat162*)(hi + i)     = ph0;
    *(__nv_bfloat162*)(hi + i + 2) = ph1;
    *(__nv_bfloat162*)(lo + i)     = pl0;
    *(__nv_bfloat162*)(lo + i + 2) = pl1;
}

// ---------------------------------------------------------------------------
// transpose + split: in [R][C] fp32 -> out [C][R] bf16 hi/lo. block (32,8)
// ---------------------------------------------------------------------------
__global__ __launch_bounds__(256)
void transpose_split(const float* __restrict__ in, __nv_bfloat16* __restrict__ oh,
                     __nv_bfloat16* __restrict__ ol, int R, int C,
                     long long sIn, long long sOut)
{
    __shared__ float tile[32][33];
    const int c0 = blockIdx.x * 32, r0 = blockIdx.y * 32, z = blockIdx.z;
    in += (size_t)z * sIn; oh += (size_t)z * sOut; ol += (size_t)z * sOut;
    const int tx = threadIdx.x, ty = threadIdx.y;
#pragma unroll
    for (int j = 0; j < 4; j++)
        tile[ty + 8 * j][tx] = in[(size_t)(r0 + ty + 8 * j) * C + c0 + tx];
    __syncthreads();
#pragma unroll
    for (int j = 0; j < 4; j++) {
        float v = tile[tx][ty + 8 * j];
        __nv_bfloat16 h = __float2bfloat16(v);
        size_t o = (size_t)(c0 + ty + 8 * j) * R + r0 + tx;
        oh[o] = h;
        ol[o] = __float2bfloat16(v - __bfloat162float(h));
    }
}

// ---------------------------------------------------------------------------
// Row softmax on bf16 S -> bf16 hi/lo P. grid (4096, 1, B), 256 threads.
// Fully 16B-vectorized: each thread owns 16 contiguous elems (2 x uint4).
// ---------------------------------------------------------------------------
__global__ __launch_bounds__(256)
void softmax_split_b(const __nv_bfloat16* __restrict__ S,
                     __nv_bfloat16* __restrict__ Ph, __nv_bfloat16* __restrict__ Pl)
{
    const size_t row = (size_t)blockIdx.z * N_ + blockIdx.x;
    const uint4* r4 = (const uint4*)(S + row * N_);      // 512 uint4 per row
    uint4* ph4 = (uint4*)(Ph + row * N_);
    uint4* pl4 = (uint4*)(Pl + row * N_);
    const int tid = threadIdx.x, lane = tid & 31, wid = tid >> 5;
    __shared__ float red[8];
    __shared__ float bval;

    uint4 u[2];
    u[0] = r4[tid];
    u[1] = r4[tid + 256];
    float v[16];
#pragma unroll
    for (int q = 0; q < 2; q++) {
        const uint32_t* w = (const uint32_t*)&u[q];
#pragma unroll
        for (int j = 0; j < 4; j++) {
            float2 f = __bfloat1622float2(*(const __nv_bfloat162*)&w[j]);
            v[q * 8 + j * 2]     = f.x;
            v[q * 8 + j * 2 + 1] = f.y;
        }
    }

    float mx = v[0];
#pragma unroll
    for (int j = 1; j < 16; j++) mx = fmaxf(mx, v[j]);
#pragma unroll
    for (int off = 16; off; off >>= 1)
        mx = fmaxf(mx, __shfl_xor_sync(0xffffffffu, mx, off));
    if (lane == 0) red[wid] = mx;
    __syncthreads();
    if (tid == 0) {
        float m = red[0];
#pragma unroll
        for (int i = 1; i < 8; i++) m = fmaxf(m, red[i]);
        bval = m;
    }
    __syncthreads();
    mx = bval;

    float s = 0.f;
#pragma unroll
    for (int j = 0; j < 16; j++) { v[j] = __expf(v[j] - mx); s += v[j]; }
#pragma unroll
    for (int off = 16; off; off >>= 1)
        s += __shfl_xor_sync(0xffffffffu, s, off);
    if (lane == 0) red[wid] = s;
    __syncthreads();
    if (tid == 0) {
        float t = 0.f;
#pragma unroll
        for (int i = 0; i < 8; i++) t += red[i];
        bval = 1.f / t;
    }
    __syncthreads();
    const float inv = bval;

    uint4 oh[2], ol[2];
#pragma unroll
    for (int q = 0; q < 2; q++) {
        uint32_t* wh = (uint32_t*)&oh[q];
        uint32_t* wl = (uint32_t*)&ol[q];
#pragma unroll
        for (int j = 0; j < 4; j++) {
            float a = v[q * 8 + j * 2] * inv;
            float b = v[q * 8 + j * 2 + 1] * inv;
            __nv_bfloat16 ha = __float2bfloat16(a), hb = __float2bfloat16(b);
            __nv_bfloat162 hp(ha, hb);
            __nv_bfloat162 lp(__float2bfloat16(a - __bfloat162float(ha)),
                              __float2bfloat16(b - __bfloat162float(hb)));
            wh[j] = *(uint32_t*)&hp;
            wl[j] = *(uint32_t*)&lp;
        }
    }
    ph4[tid]       = oh[0];
    ph4[tid + 256] = oh[1];
    pl4[tid]       = ol[0];
    pl4[tid + 256] = ol[1];
}

// ---------------------------------------------------------------------------
// Hyperedge branch
// ---------------------------------------------------------------------------
__global__ __launch_bounds__(256)
void edge_mean_kernel(const float* __restrict__ x, const int* __restrict__ Hm)
{
    const int e = blockIdx.x, b = blockIdx.y, f = threadIdx.x;
    const float* xb = x + (size_t)b * N_ * F_;
    float sum = 0.f;
    int cnt = 0;
    for (int n = 0; n < N_; n++) {
        if (Hm[(size_t)n * E_ + e]) {
            sum += xb[(size_t)n * F_ + f];
            cnt++;
        }
    }
    const float deg = (float)cnt;
    g_mean[((size_t)b * MAXE + e) * F_ + f] = sum / fmaxf(deg, 1.0f);
    if (f == 0 && b == 0) g_deg[e] = deg;
}

__global__ __launch_bounds__(128)
void ctx_kernel(const float* __restrict__ m1w, const float* __restrict__ m1b,
                const float* __restrict__ m2w, const float* __restrict__ m2b,
                const float* __restrict__ m3w, const float* __restrict__ m3b)
{
    const int e = blockIdx.x, b = blockIdx.y, t = threadIdx.x;
    __shared__ float ms[F_];
    __shared__ float h1[H1_];
    __shared__ float h2[H2_];
    __shared__ float red[4];

    const float* mp = g_mean + ((size_t)b * MAXE + e) * F_;
    ms[t]       = mp[t];
    ms[t + 128] = mp[t + 128];
    __syncthreads();

    float s = m1b[t];
    for (int k = 0; k < F_; k++) s += ms[k] * m1w[k * H1_ + t];
    h1[t] = fmaxf(s, 0.f);
    __syncthreads();

    if (t < H2_) {
        float s2 = m2b[t];
        for (int k = 0; k < H1_; k++) s2 += h1[k] * m2w[k * H2_ + t];
        h2[t] = fmaxf(s2, 0.f);
    }
    __syncthreads();

    float p = (t < H2_) ? h2[t] * m3w[t] : 0.f;
#pragma unroll
    for (int off = 16; off; off >>= 1)
        p += __shfl_xor_sync(0xffffffffu, p, off);
    if ((t & 31) == 0) red[t >> 5] = p;
    __syncthreads();
    if (t == 0)
        g_ctx[b * MAXE + e] = red[0] + red[1] + red[2] + red[3] + m3b[0];
}

__global__ __launch_bounds__(256)
void aw_kernel(const float* __restrict__ x, const int* __restrict__ Hm,
               const float* __restrict__ cw, const float* __restrict__ cb,
               const float* __restrict__ hb, const float* __restrict__ alpha,
               float* __restrict__ out)
{
    const int n = blockIdx.x, b = blockIdx.y, t = threadIdx.x;
    __shared__ float red[8];
    __shared__ float compat_s;

    float p = x[((size_t)b * N_ + n) * F_ + t] * cw[t];
#pragma unroll
    for (int off = 16; off; off >>= 1)
        p += __shfl_xor_sync(0xffffffffu, p, off);
    if ((t & 31) == 0) red[t >> 5] = p;
    __syncthreads();
    if (t == 0) {
        float s = 0.f;
#pragma unroll
        for (int i = 0; i < 8; i++) s += red[i];
        compat_s = s + cb[0] + hb[0];
    }
    __syncthreads();

    float val = 0.f;
    if (t < MAXE) {
        if (Hm[(size_t)n * E_ + t] && g_deg[t] > 1.0f) {
            float z = compat_s + alpha[0] * g_ctx[b * MAXE + t];
            val = 1.f / (1.f + __expf(-z));
        }
    }
    out[((size_t)b * N_ + n) * OUTC + t] = val;
}

// ---------------------------------------------------------------------------
// Launch
// ---------------------------------------------------------------------------
extern "C" void kernel_launch(void* const* d_in, const int* in_sizes, int n_in,
                              void* d_out, int out_size)
{
    const float* x      = (const float*)d_in[0];
    const int*   Hm     = (const int*)  d_in[1];
    const float* weight = (const float*)d_in[2];
    const float* bias   = (const float*)d_in[3];
    const float* Wn_w   = (const float*)d_in[4];
    const float* Wn_b   = (const float*)d_in[5];
    const float* m1_w   = (const float*)d_in[6];
    const float* m1_b   = (const float*)d_in[7];
    const float* m2_w   = (const float*)d_in[8];
    const float* m2_b   = (const float*)d_in[9];
    const float* m3_w   = (const float*)d_in[10];
    const float* m3_b   = (const float*)d_in[11];
    const float* c_w    = (const float*)d_in[12];
    const float* c_b    = (const float*)d_in[13];
    const float* hedgeb = (const float*)d_in[14];
    const float* alpha  = (const float*)d_in[15];
    float* out = (float*)d_out;

    float* v;
    __nv_bfloat16 *Sb, *xh, *xl, *xph, *xpl, *vth, *vtl, *Ph, *Pl;
    __nv_bfloat16 *wth, *wtl, *wnth, *wntl;
    cudaGetSymbolAddress((void**)&v,   g_v);
    cudaGetSymbolAddress((void**)&Sb,  g_Sb);
    cudaGetSymbolAddress((void**)&xh,  g_xh);
    cudaGetSymbolAddress((void**)&xl,  g_xl);
    cudaGetSymbolAddress((void**)&xph, g_xph);
    cudaGetSymbolAddress((void**)&xpl, g_xpl);
    cudaGetSymbolAddress((void**)&vth, g_vth);
    cudaGetSymbolAddress((void**)&vtl, g_vtl);
    cudaGetSymbolAddress((void**)&Ph,  g_Ph);
    cudaGetSymbolAddress((void**)&Pl,  g_Pl);
    cudaGetSymbolAddress((void**)&wth, g_wth);
    cudaGetSymbolAddress((void**)&wtl, g_wtl);
    cudaGetSymbolAddress((void**)&wnth, g_wnth);
    cudaGetSymbolAddress((void**)&wntl, g_wntl);

    cudaFuncSetAttribute(gemm_bf16s<3, 0>,
                         cudaFuncAttributeMaxDynamicSharedMemorySize, GEMM_SMEM);
    cudaFuncSetAttribute(gemm_bf16s<3, 2>,
                         cudaFuncAttributeMaxDynamicSharedMemorySize, GEMM_SMEM);
    cudaFuncSetAttribute(gemm_bf16s<2, 1>,
                         cudaFuncAttributeMaxDynamicSharedMemorySize, GEMM_SMEM);

    const int nx = B_ * N_ * F_;   // 4M elements

    // hyperedge branch (independent)
    edge_mean_kernel<<<dim3(MAXE, B_), 256>>>(x, Hm);
    ctx_kernel<<<dim3(MAXE, B_), 128>>>(m1_w, m1_b, m2_w, m2_b, m3_w, m3_b);
    aw_kernel<<<dim3(N_, B_), 256>>>(x, Hm, c_w, c_b, hedgeb, alpha, out);

    // input conversions
    conv_split<<<nx / 4 / 256, 256>>>(x, xh, xl, nx);
    transpose_split<<<dim3(8, 8, 1), dim3(32, 8)>>>(weight, wth, wtl, F_, F_, 0, 0);
    transpose_split<<<dim3(8, 8, 1), dim3(32, 8)>>>(Wn_w, wnth, wntl, F_, F_, 0, 0);

    // projections: xp = x@Wn_w + Wn_b (split emitted directly) ; v = x@weight (fp32)
    gemm_bf16s<3, 2><<<dim3(F_ / 128, (B_ * N_) / 128, 1), 256, GEMM_SMEM>>>(
        xh, xl, wnth, wntl, xph, xpl, Wn_b, F_, F_, 0, 0, 0, 1.0f);
    gemm_bf16s<3, 0><<<dim3(F_ / 128, (B_ * N_) / 128, 1), 256, GEMM_SMEM>>>(
        xh, xl, wth, wtl, v, nullptr, nullptr, F_, F_, 0, 0, 0, 1.0f);

    // v transposed per batch -> bf16 hi/lo
    transpose_split<<<dim3(F_ / 32, N_ / 32, B_), dim3(32, 8)>>>(
        v, vth, vtl, N_, F_, (long long)N_ * F_, (long long)F_ * N_);

    // S = xp @ xp^T / 16 -> bf16 (2-pass split: AhBh + AlBh)
    gemm_bf16s<2, 1><<<dim3(N_ / 128, N_ / 128, B_), 256, GEMM_SMEM>>>(
        xph, xpl, xph, xpl, Sb, nullptr, nullptr, F_, N_,
        (long long)N_ * F_, (long long)N_ * F_, (long long)N_ * N_, 0.0625f);

    // P = softmax(S) -> bf16 hi/lo
    softmax_split_b<<<dim3(N_, 1, B_), 256>>>(Sb, Ph, Pl);

    // y = P @ V + bias -> out[..., E:E+F]
    gemm_bf16s<3, 0><<<dim3(F_ / 128, N_ / 128, B_), 256, GEMM_SMEM>>>(
        Ph, Pl, vth, vtl, out + E_, nullptr, bias, N_, OUTC,
        (long long)N_ * N_, (long long)F_ * N_, (long long)N_ * OUTC, 1.0f);
}

// round 8
// speedup vs baseline: 2.7049x; 1.0834x over previous
#include <cuda_runtime.h>
#include <cuda_bf16.h>
#include <cstdint>
#include <cstddef>

// Problem constants
#define B_   4
#define N_   4096
#define E_   256
#define F_   256
#define MAXE 50
#define H1_  128
#define H2_  64
#define OUTC 512

// ---------------------------------------------------------------------------
// Static device scratch
// ---------------------------------------------------------------------------
__device__ float g_v [B_ * N_ * F_];                 // v fp32 (16 MB)
__device__ __nv_bfloat16 g_Sb[67108864];             // scores bf16 (128 MB)
__device__ __nv_bfloat16 g_xh [B_ * N_ * F_];        // x hi
__device__ __nv_bfloat16 g_xl [B_ * N_ * F_];        // x lo
__device__ __nv_bfloat16 g_xph[B_ * N_ * F_];        // xp hi
__device__ __nv_bfloat16 g_xpl[B_ * N_ * F_];
__device__ __nv_bfloat16 g_vth[B_ * F_ * N_];        // v^T hi  [b][256][4096]
__device__ __nv_bfloat16 g_vtl[B_ * F_ * N_];
__device__ __nv_bfloat16 g_Ph [67108864];            // softmax(S) hi (128 MB)
__device__ __nv_bfloat16 g_Pl [67108864];            // softmax(S) lo (128 MB)
__device__ __nv_bfloat16 g_wth [F_ * F_], g_wtl [F_ * F_];   // weight^T hi/lo
__device__ __nv_bfloat16 g_wnth[F_ * F_], g_wntl[F_ * F_];   // Wn_w^T hi/lo
__device__ float g_mean[B_ * MAXE * F_];
__device__ float g_ctx [B_ * MAXE];
__device__ float g_deg [MAXE];

// ---------------------------------------------------------------------------
// PTX helpers (base sm_100-safe: mma.sync / ldmatrix / cp.async)
// ---------------------------------------------------------------------------
__device__ __forceinline__ uint32_t smem_u32(const void* p) {
    uint32_t a;
    asm("{ .reg .u64 t; cvta.to.shared.u64 t, %1; cvt.u32.u64 %0, t; }"
        : "=r"(a) : "l"(p));
    return a;
}
__device__ __forceinline__ void cp_async16(uint32_t s, const void* g) {
    asm volatile("cp.async.cg.shared.global [%0], [%1], 16;\n"
        :: "r"(s), "l"((unsigned long long)__cvta_generic_to_global(g)) : "memory");
}
__device__ __forceinline__ void cp_commit() {
    asm volatile("cp.async.commit_group;\n" ::: "memory");
}
__device__ __forceinline__ void cp_wait0() {
    asm volatile("cp.async.wait_group 0;\n" ::: "memory");
}
__device__ __forceinline__ void cp_wait1() {
    asm volatile("cp.async.wait_group 1;\n" ::: "memory");
}
__device__ __forceinline__ void ldmatrix_x4(uint32_t* r, uint32_t addr) {
    asm volatile("ldmatrix.sync.aligned.m8n8.x4.shared.b16 {%0,%1,%2,%3}, [%4];\n"
        : "=r"(r[0]), "=r"(r[1]), "=r"(r[2]), "=r"(r[3]) : "r"(addr));
}
__device__ __forceinline__ void mma_bf16(float* d, const uint32_t* a,
                                         uint32_t b0, uint32_t b1) {
    asm volatile(
        "mma.sync.aligned.m16n8k16.row.col.f32.bf16.bf16.f32 "
        "{%0,%1,%2,%3}, {%4,%5,%6,%7}, {%8,%9}, {%0,%1,%2,%3};\n"
        : "+f"(d[0]), "+f"(d[1]), "+f"(d[2]), "+f"(d[3])
        : "r"(a[0]), "r"(a[1]), "r"(a[2]), "r"(a[3]), "r"(b0), "r"(b1));
}

// ---------------------------------------------------------------------------
// bf16 split GEMM via mma.sync: D[m][n] = scale*sum_k A[m,k]*B[n,k] (+bias)
// NPASS=3: AhBh + AlBh + AhBl.  NPASS=2: AhBh + AlBh.
// OMODE=0: fp32 out. OMODE=1: bf16 out. OMODE=2: bf16 hi/lo out.
// SYM=1: A==B from the same matrix; grid.x enumerates upper-triangle 128x128
//        tile pairs (NT=32 row blocks -> 528); each CTA writes its tile and
//        the transposed mirror (requires OMODE==1).
// CTA tile 128x128, K-chunk 64, 256 threads (8 warps 2m x 4n, warp 64x32).
// Smem: 3 stages x (A 16KB + B 16KB) = 96KB, XOR-swizzled for ldmatrix.
// Pipeline: depth-2 prefetch, cp.async.wait_group 1 (0 on the last chunk).
// ---------------------------------------------------------------------------
#define GEMM_SMEM (3 * 32768)

template <int NPASS, int OMODE, int SYM>
__global__ __launch_bounds__(256)
void gemm_bf16s(const __nv_bfloat16* __restrict__ Ah, const __nv_bfloat16* __restrict__ Al,
                const __nv_bfloat16* __restrict__ Bh, const __nv_bfloat16* __restrict__ Bl,
                void* __restrict__ C0p, void* __restrict__ C1p,
                const float* __restrict__ bias, int K, int ldc,
                long long sA, long long sB, long long sC, float scale)
{
    extern __shared__ __align__(16) char smem[];
    const uint32_t sbase = smem_u32(smem);
    const int tid = threadIdx.x;
    const int lane = tid & 31;
    const int wid = tid >> 5;
    const int wm = wid & 1;        // 2 warp rows  (64 rows each)
    const int wn = wid >> 1;       // 4 warp cols  (32 cols each)

    size_t Ms, Ns;
    int ibl = 0, jbl = 0;
    if (SYM) {
        const int NT = 32;
        int t = blockIdx.x;
        int i = (int)((2.f * NT + 1.f -
                       sqrtf((2.f * NT + 1.f) * (2.f * NT + 1.f) - 8.f * t)) * 0.5f);
        while ((i + 1) * NT - ((i + 1) * i) / 2 <= t) i++;
        while (i * NT - (i * (i - 1)) / 2 > t) i--;
        int j = i + (t - (i * NT - (i * (i - 1)) / 2));
        ibl = i; jbl = j;
        Ms = (size_t)i * 128;
        Ns = (size_t)j * 128;
    } else {
        Ms = (size_t)blockIdx.y * 128;
        Ns = (size_t)blockIdx.x * 128;
    }
    const int z = blockIdx.z;
    const __nv_bfloat16* pAh = Ah + (size_t)z * sA + Ms * K;
    const __nv_bfloat16* pAl = Al + (size_t)z * sA + Ms * K;
    const __nv_bfloat16* pBh = Bh + (size_t)z * sB + Ns * K;
    const __nv_bfloat16* pBl = Bl + (size_t)z * sB + Ns * K;

    const int KC = K >> 6;          // 64-wide K chunks per pass
    const int T = NPASS * KC;

    float acc[4][4][4];
#pragma unroll
    for (int i = 0; i < 4; i++)
#pragma unroll
        for (int j = 0; j < 4; j++)
#pragma unroll
            for (int k = 0; k < 4; k++) acc[i][j][k] = 0.f;

    auto load_chunk = [&](int t) {
        const int pass = t / KC;
        const int kk = (t - pass * KC) << 6;
        const __nv_bfloat16* pA = (pass == 1) ? pAl : pAh;
        const __nv_bfloat16* pB = (pass == 2) ? pBl : pBh;
        const uint32_t st = sbase + (t % 3) * 32768;
#pragma unroll
        for (int i = 0; i < 4; i++) {
            int idx = i * 256 + tid;
            int row = idx >> 3, c = idx & 7;
            uint32_t sa = st + row * 128 + ((c ^ (row & 7)) << 4);
            cp_async16(sa, pA + (size_t)row * K + kk + c * 8);
        }
#pragma unroll
        for (int i = 0; i < 4; i++) {
            int idx = i * 256 + tid;
            int row = idx >> 3, c = idx & 7;
            uint32_t sa = st + 16384 + row * 128 + ((c ^ (row & 7)) << 4);
            cp_async16(sa, pB + (size_t)row * K + kk + c * 8);
        }
        cp_commit();
    };

    load_chunk(0);
    load_chunk(1);

#pragma unroll 1
    for (int t = 0; t < T; t++) {
        if (t + 1 < T) cp_wait1(); else cp_wait0();
        __syncthreads();
        if (t + 2 < T) load_chunk(t + 2);

        const uint32_t Ab = sbase + (t % 3) * 32768;
        const uint32_t Bb = Ab + 16384;
#pragma unroll
        for (int ks = 0; ks < 4; ks++) {
            uint32_t afr[4][4];
#pragma unroll
            for (int mt = 0; mt < 4; mt++) {
                int arow = wm * 64 + mt * 16 + (lane & 15);
                int c = ks * 2 + (lane >> 4);
                ldmatrix_x4(afr[mt], Ab + arow * 128 + ((c ^ (arow & 7)) << 4));
            }
            uint32_t bfr[2][4];
#pragma unroll
            for (int np = 0; np < 2; np++) {
                int nrow = wn * 32 + np * 16 + (lane & 7) + ((lane >> 4) << 3);
                int c = ks * 2 + ((lane >> 3) & 1);
                ldmatrix_x4(bfr[np], Bb + nrow * 128 + ((c ^ (nrow & 7)) << 4));
            }
#pragma unroll
            for (int mt = 0; mt < 4; mt++)
#pragma unroll
                for (int nt = 0; nt < 4; nt++)
                    mma_bf16(acc[mt][nt], afr[mt],
                             bfr[nt >> 1][(nt & 1) * 2],
                             bfr[nt >> 1][(nt & 1) * 2 + 1]);
        }
    }

    // stage for SYM transpose (reuses pipeline smem after all compute done)
    __nv_bfloat16* stg = (__nv_bfloat16*)smem;     // [128][136]
    if (SYM) __syncthreads();

    // epilogue
    const int tg = lane >> 2, tq = lane & 3;
#pragma unroll
    for (int mt = 0; mt < 4; mt++) {
#pragma unroll
        for (int nt = 0; nt < 4; nt++) {
            int r0 = wm * 64 + mt * 16 + tg;
            int cc = wn * 32 + nt * 8 + tq * 2;
            float b0 = 0.f, b1 = 0.f;
            if (bias) { b0 = bias[Ns + cc]; b1 = bias[Ns + cc + 1]; }
            float v00 = acc[mt][nt][0] * scale + b0;
            float v01 = acc[mt][nt][1] * scale + b1;
            float v10 = acc[mt][nt][2] * scale + b0;
            float v11 = acc[mt][nt][3] * scale + b1;
            if (OMODE == 0) {
                float* pC = (float*)C0p + (size_t)z * sC + Ms * ldc + Ns;
                float2 w0 = { v00, v01 }, w1 = { v10, v11 };
                *(float2*)(pC + (size_t)r0 * ldc + cc)       = w0;
                *(float2*)(pC + (size_t)(r0 + 8) * ldc + cc) = w1;
            } else if (OMODE == 1) {
                __nv_bfloat16* pC = (__nv_bfloat16*)C0p + (size_t)z * sC + Ms * ldc + Ns;
                __nv_bfloat16 h00 = __float2bfloat16(v00), h01 = __float2bfloat16(v01);
                __nv_bfloat16 h10 = __float2bfloat16(v10), h11 = __float2bfloat16(v11);
                *(__nv_bfloat162*)(pC + (size_t)r0 * ldc + cc) = __nv_bfloat162(h00, h01);
                *(__nv_bfloat162*)(pC + (size_t)(r0 + 8) * ldc + cc) = __nv_bfloat162(h10, h11);
                if (SYM) {
                    stg[r0 * 136 + cc]           = h00;
                    stg[r0 * 136 + cc + 1]       = h01;
                    stg[(r0 + 8) * 136 + cc]     = h10;
                    stg[(r0 + 8) * 136 + cc + 1] = h11;
                }
            } else {
                __nv_bfloat16* pH = (__nv_bfloat16*)C0p + (size_t)z * sC + Ms * ldc + Ns;
                __nv_bfloat16* pL = (__nv_bfloat16*)C1p + (size_t)z * sC + Ms * ldc + Ns;
                __nv_bfloat16 h00 = __float2bfloat16(v00), h01 = __float2bfloat16(v01);
                __nv_bfloat16 h10 = __float2bfloat16(v10), h11 = __float2bfloat16(v11);
                *(__nv_bfloat162*)(pH + (size_t)r0 * ldc + cc) = __nv_bfloat162(h00, h01);
                *(__nv_bfloat162*)(pH + (size_t)(r0 + 8) * ldc + cc) = __nv_bfloat162(h10, h11);
                *(__nv_bfloat162*)(pL + (size_t)r0 * ldc + cc) =
                    __nv_bfloat162(__float2bfloat16(v00 - __bfloat162float(h00)),
                                   __float2bfloat16(v01 - __bfloat162float(h01)));
                *(__nv_bfloat162*)(pL + (size_t)(r0 + 8) * ldc + cc) =
                    __nv_bfloat162(__float2bfloat16(v10 - __bfloat162float(h10)),
                                   __float2bfloat16(v11 - __bfloat162float(h11)));
            }
        }
    }

    if (SYM && ibl != jbl) {
        __syncthreads();
        // write transposed mirror tile at row block jbl, col block ibl
        __nv_bfloat16* pT = (__nv_bfloat16*)C0p + (size_t)z * sC + Ns * ldc + Ms;
        const int orow = tid >> 1;        // 0..127 (transposed row = original col)
        const int half = tid & 1;
#pragma unroll
        for (int q = 0; q < 8; q++) {
            int c0 = half * 64 + q * 8;   // original-row index span
            __nv_bfloat16 tmp[8];
#pragma unroll
            for (int e = 0; e < 8; e++)
                tmp[e] = stg[(c0 + e) * 136 + orow];
            *(uint4*)(pT + (size_t)orow * ldc + c0) = *(uint4*)tmp;
        }
    }
}

// ---------------------------------------------------------------------------
// fp32 -> (bf16 hi, bf16 lo) split, 4 elements/thread
// ---------------------------------------------------------------------------
__global__ __launch_bounds__(256)
void conv_split(const float* __restrict__ in, __nv_bfloat16* __restrict__ hi,
                __nv_bfloat16* __restrict__ lo, int n)
{
    int i = (blockIdx.x * 256 + threadIdx.x) * 4;
    if (i >= n) return;
    float4 v = *(const float4*)(in + i);
    __nv_bfloat16 h0 = __float2bfloat16(v.x), h1 = __float2bfloat16(v.y);
    __nv_bfloat16 h2 = __float2bfloat16(v.z), h3 = __float2bfloat16(v.w);
    __nv_bfloat162 ph0(h0, h1), ph1(h2, h3);
    __nv_bfloat162 pl0(__float2bfloat16(v.x - __bfloat162float(h0)),
                       __float2bfloat16(v.y - __bfloat162float(h1)));
    __nv_bfloat162 pl1(__float2bfloat16(v.z - __bfloat162float(h2)),
                       __float2bfloat16(v.w - __bfloat162float(h3)));
    *(__nv_bfloat162*)(hi + i)     = ph0;
    *(__nv_bfloat162*)(hi + i + 2) = ph1;
    *(__nv_bfloat162*)(lo + i)     = pl0;
    *(__nv_bfloat162*)(lo + i + 2) = pl1;
}

// ---------------------------------------------------------------------------
// transpose + split: in [R][C] fp32 -> out [C][R] bf16 hi/lo. block (32,8)
// ---------------------------------------------------------------------------
__global__ __launch_bounds__(256)
void transpose_split(const float* __restrict__ in, __nv_bfloat16* __restrict__ oh,
                     __nv_bfloat16* __restrict__ ol, int R, int C,
                     long long sIn, long long sOut)
{
    __shared__ float tile[32][33];
    const int c0 = blockIdx.x * 32, r0 = blockIdx.y * 32, z = blockIdx.z;
    in += (size_t)z * sIn; oh += (size_t)z * sOut; ol += (size_t)z * sOut;
    const int tx = threadIdx.x, ty = threadIdx.y;
#pragma unroll
    for (int j = 0; j < 4; j++)
        tile[ty + 8 * j][tx] = in[(size_t)(r0 + ty + 8 * j) * C + c0 + tx];
    __syncthreads();
#pragma unroll
    for (int j = 0; j < 4; j++) {
        float v = tile[tx][ty + 8 * j];
        __nv_bfloat16 h = __float2bfloat16(v);
        size_t o = (size_t)(c0 + ty + 8 * j) * R + r0 + tx;
        oh[o] = h;
        ol[o] = __float2bfloat16(v - __bfloat162float(h));
    }
}

// ---------------------------------------------------------------------------
// Row softmax on bf16 S -> bf16 hi/lo P. grid (4096, 1, B), 256 threads.
// Fully 16B-vectorized: each thread owns 16 contiguous elems (2 x uint4).
// ---------------------------------------------------------------------------
__global__ __launch_bounds__(256)
void softmax_split_b(const __nv_bfloat16* __restrict__ S,
                     __nv_bfloat16* __restrict__ Ph, __nv_bfloat16* __restrict__ Pl)
{
    const size_t row = (size_t)blockIdx.z * N_ + blockIdx.x;
    const uint4* r4 = (const uint4*)(S + row * N_);      // 512 uint4 per row
    uint4* ph4 = (uint4*)(Ph + row * N_);
    uint4* pl4 = (uint4*)(Pl + row * N_);
    const int tid = threadIdx.x, lane = tid & 31, wid = tid >> 5;
    __shared__ float red[8];
    __shared__ float bval;

    uint4 u[2];
    u[0] = r4[tid];
    u[1] = r4[tid + 256];
    float v[16];
#pragma unroll
    for (int q = 0; q < 2; q++) {
        const uint32_t* w = (const uint32_t*)&u[q];
#pragma unroll
        for (int j = 0; j < 4; j++) {
            float2 f = __bfloat1622float2(*(const __nv_bfloat162*)&w[j]);
            v[q * 8 + j * 2]     = f.x;
            v[q * 8 + j * 2 + 1] = f.y;
        }
    }

    float mx = v[0];
#pragma unroll
    for (int j = 1; j < 16; j++) mx = fmaxf(mx, v[j]);
#pragma unroll
    for (int off = 16; off; off >>= 1)
        mx = fmaxf(mx, __shfl_xor_sync(0xffffffffu, mx, off));
    if (lane == 0) red[wid] = mx;
    __syncthreads();
    if (tid == 0) {
        float m = red[0];
#pragma unroll
        for (int i = 1; i < 8; i++) m = fmaxf(m, red[i]);
        bval = m;
    }
    __syncthreads();
    mx = bval;

    float s = 0.f;
#pragma unroll
    for (int j = 0; j < 16; j++) { v[j] = __expf(v[j] - mx); s += v[j]; }
#pragma unroll
    for (int off = 16; off; off >>= 1)
        s += __shfl_xor_sync(0xffffffffu, s, off);
    if (lane == 0) red[wid] = s;
    __syncthreads();
    if (tid == 0) {
        float t = 0.f;
#pragma unroll
        for (int i = 0; i < 8; i++) t += red[i];
        bval = 1.f / t;
    }
    __syncthreads();
    const float inv = bval;

    uint4 oh[2], ol[2];
#pragma unroll
    for (int q = 0; q < 2; q++) {
        uint32_t* wh = (uint32_t*)&oh[q];
        uint32_t* wl = (uint32_t*)&ol[q];
#pragma unroll
        for (int j = 0; j < 4; j++) {
            float a = v[q * 8 + j * 2] * inv;
            float b = v[q * 8 + j * 2 + 1] * inv;
            __nv_bfloat16 ha = __float2bfloat16(a), hb = __float2bfloat16(b);
            __nv_bfloat162 hp(ha, hb);
            __nv_bfloat162 lp(__float2bfloat16(a - __bfloat162float(ha)),
                              __float2bfloat16(b - __bfloat162float(hb)));
            wh[j] = *(uint32_t*)&hp;
            wl[j] = *(uint32_t*)&lp;
        }
    }
    ph4[tid]       = oh[0];
    ph4[tid + 256] = oh[1];
    pl4[tid]       = ol[0];
    pl4[tid + 256] = ol[1];
}

// ---------------------------------------------------------------------------
// Hyperedge branch
// ---------------------------------------------------------------------------
__global__ __launch_bounds__(256)
void edge_mean_kernel(const float* __restrict__ x, const int* __restrict__ Hm)
{
    const int e = blockIdx.x, b = blockIdx.y, f = threadIdx.x;
    const float* xb = x + (size_t)b * N_ * F_;
    float sum = 0.f;
    int cnt = 0;
    for (int n = 0; n < N_; n++) {
        if (Hm[(size_t)n * E_ + e]) {
            sum += xb[(size_t)n * F_ + f];
            cnt++;
        }
    }
    const float deg = (float)cnt;
    g_mean[((size_t)b * MAXE + e) * F_ + f] = sum / fmaxf(deg, 1.0f);
    if (f == 0 && b == 0) g_deg[e] = deg;
}

__global__ __launch_bounds__(128)
void ctx_kernel(const float* __restrict__ m1w, const float* __restrict__ m1b,
                const float* __restrict__ m2w, const float* __restrict__ m2b,
                const float* __restrict__ m3w, const float* __restrict__ m3b)
{
    const int e = blockIdx.x, b = blockIdx.y, t = threadIdx.x;
    __shared__ float ms[F_];
    __shared__ float h1[H1_];
    __shared__ float h2[H2_];
    __shared__ float red[4];

    const float* mp = g_mean + ((size_t)b * MAXE + e) * F_;
    ms[t]       = mp[t];
    ms[t + 128] = mp[t + 128];
    __syncthreads();

    float s = m1b[t];
    for (int k = 0; k < F_; k++) s += ms[k] * m1w[k * H1_ + t];
    h1[t] = fmaxf(s, 0.f);
    __syncthreads();

    if (t < H2_) {
        float s2 = m2b[t];
        for (int k = 0; k < H1_; k++) s2 += h1[k] * m2w[k * H2_ + t];
        h2[t] = fmaxf(s2, 0.f);
    }
    __syncthreads();

    float p = (t < H2_) ? h2[t] * m3w[t] : 0.f;
#pragma unroll
    for (int off = 16; off; off >>= 1)
        p += __shfl_xor_sync(0xffffffffu, p, off);
    if ((t & 31) == 0) red[t >> 5] = p;
    __syncthreads();
    if (t == 0)
        g_ctx[b * MAXE + e] = red[0] + red[1] + red[2] + red[3] + m3b[0];
}

__global__ __launch_bounds__(256)
void aw_kernel(const float* __restrict__ x, const int* __restrict__ Hm,
               const float* __restrict__ cw, const float* __restrict__ cb,
               const float* __restrict__ hb, const float* __restrict__ alpha,
               float* __restrict__ out)
{
    const int n = blockIdx.x, b = blockIdx.y, t = threadIdx.x;
    __shared__ float red[8];
    __shared__ float compat_s;

    float p = x[((size_t)b * N_ + n) * F_ + t] * cw[t];
#pragma unroll
    for (int off = 16; off; off >>= 1)
        p += __shfl_xor_sync(0xffffffffu, p, off);
    if ((t & 31) == 0) red[t >> 5] = p;
    __syncthreads();
    if (t == 0) {
        float s = 0.f;
#pragma unroll
        for (int i = 0; i < 8; i++) s += red[i];
        compat_s = s + cb[0] + hb[0];
    }
    __syncthreads();

    float val = 0.f;
    if (t < MAXE) {
        if (Hm[(size_t)n * E_ + t] && g_deg[t] > 1.0f) {
            float z = compat_s + alpha[0] * g_ctx[b * MAXE + t];
            val = 1.f / (1.f + __expf(-z));
        }
    }
    out[((size_t)b * N_ + n) * OUTC + t] = val;
}

// ---------------------------------------------------------------------------
// Launch
// ---------------------------------------------------------------------------
extern "C" void kernel_launch(void* const* d_in, const int* in_sizes, int n_in,
                              void* d_out, int out_size)
{
    const float* x      = (const float*)d_in[0];
    const int*   Hm     = (const int*)  d_in[1];
    const float* weight = (const float*)d_in[2];
    const float* bias   = (const float*)d_in[3];
    const float* Wn_w   = (const float*)d_in[4];
    const float* Wn_b   = (const float*)d_in[5];
    const float* m1_w   = (const float*)d_in[6];
    const float* m1_b   = (const float*)d_in[7];
    const float* m2_w   = (const float*)d_in[8];
    const float* m2_b   = (const float*)d_in[9];
    const float* m3_w   = (const float*)d_in[10];
    const float* m3_b   = (const float*)d_in[11];
    const float* c_w    = (const float*)d_in[12];
    const float* c_b    = (const float*)d_in[13];
    const float* hedgeb = (const float*)d_in[14];
    const float* alpha  = (const float*)d_in[15];
    float* out = (float*)d_out;

    float* v;
    __nv_bfloat16 *Sb, *xh, *xl, *xph, *xpl, *vth, *vtl, *Ph, *Pl;
    __nv_bfloat16 *wth, *wtl, *wnth, *wntl;
    cudaGetSymbolAddress((void**)&v,   g_v);
    cudaGetSymbolAddress((void**)&Sb,  g_Sb);
    cudaGetSymbolAddress((void**)&xh,  g_xh);
    cudaGetSymbolAddress((void**)&xl,  g_xl);
    cudaGetSymbolAddress((void**)&xph, g_xph);
    cudaGetSymbolAddress((void**)&xpl, g_xpl);
    cudaGetSymbolAddress((void**)&vth, g_vth);
    cudaGetSymbolAddress((void**)&vtl, g_vtl);
    cudaGetSymbolAddress((void**)&Ph,  g_Ph);
    cudaGetSymbolAddress((void**)&Pl,  g_Pl);
    cudaGetSymbolAddress((void**)&wth, g_wth);
    cudaGetSymbolAddress((void**)&wtl, g_wtl);
    cudaGetSymbolAddress((void**)&wnth, g_wnth);
    cudaGetSymbolAddress((void**)&wntl, g_wntl);

    cudaFuncSetAttribute(gemm_bf16s<3, 0, 0>,
                         cudaFuncAttributeMaxDynamicSharedMemorySize, GEMM_SMEM);
    cudaFuncSetAttribute(gemm_bf16s<3, 2, 0>,
                         cudaFuncAttributeMaxDynamicSharedMemorySize, GEMM_SMEM);
    cudaFuncSetAttribute(gemm_bf16s<2, 1, 1>,
                         cudaFuncAttributeMaxDynamicSharedMemorySize, GEMM_SMEM);

    const int nx = B_ * N_ * F_;   // 4M elements

    // hyperedge branch (independent)
    edge_mean_kernel<<<dim3(MAXE, B_), 256>>>(x, Hm);
    ctx_kernel<<<dim3(MAXE, B_), 128>>>(m1_w, m1_b, m2_w, m2_b, m3_w, m3_b);
    aw_kernel<<<dim3(N_, B_), 256>>>(x, Hm, c_w, c_b, hedgeb, alpha, out);

    // input conversions
    conv_split<<<nx / 4 / 256, 256>>>(x, xh, xl, nx);
    transpose_split<<<dim3(8, 8, 1), dim3(32, 8)>>>(weight, wth, wtl, F_, F_, 0, 0);
    transpose_split<<<dim3(8, 8, 1), dim3(32, 8)>>>(Wn_w, wnth, wntl, F_, F_, 0, 0);

    // projections: xp = x@Wn_w + Wn_b (split emitted directly) ; v = x@weight (fp32)
    gemm_bf16s<3, 2, 0><<<dim3(F_ / 128, (B_ * N_) / 128, 1), 256, GEMM_SMEM>>>(
        xh, xl, wnth, wntl, xph, xpl, Wn_b, F_, F_, 0, 0, 0, 1.0f);
    gemm_bf16s<3, 0, 0><<<dim3(F_ / 128, (B_ * N_) / 128, 1), 256, GEMM_SMEM>>>(
        xh, xl, wth, wtl, v, nullptr, nullptr, F_, F_, 0, 0, 0, 1.0f);

    // v transposed per batch -> bf16 hi/lo
    transpose_split<<<dim3(F_ / 32, N_ / 32, B_), dim3(32, 8)>>>(
        v, vth, vtl, N_, F_, (long long)N_ * F_, (long long)F_ * N_);

    // S = xp @ xp^T / 16 -> bf16, symmetric: 528 upper-triangle tiles + mirror
    gemm_bf16s<2, 1, 1><<<dim3(528, 1, B_), 256, GEMM_SMEM>>>(
        xph, xpl, xph, xpl, Sb, nullptr, nullptr, F_, N_,
        (long long)N_ * F_, (long long)N_ * F_, (long long)N_ * N_, 0.0625f);

    // P = softmax(S) -> bf16 hi/lo
    softmax_split_b<<<dim3(N_, 1, B_), 256>>>(Sb, Ph, Pl);

    // y = P @ V + bias -> out[..., E:E+F]
    gemm_bf16s<3, 0, 0><<<dim3(F_ / 128, N_ / 128, B_), 256, GEMM_SMEM>>>(
        Ph, Pl, vth, vtl, out + E_, nullptr, bias, N_, OUTC,
        (long long)N_ * N_, (long long)F_ * N_, (long long)N_ * OUTC, 1.0f);
}

// round 10
// speedup vs baseline: 2.7129x; 1.0030x over previous
#include <cuda_runtime.h>
#include <cuda_bf16.h>
#include <cstdint>
#include <cstddef>

// Problem constants
#define B_   4
#define N_   4096
#define E_   256
#define F_   256
#define MAXE 50
#define H1_  128
#define H2_  64
#define OUTC 512

// ---------------------------------------------------------------------------
// Static device scratch
// ---------------------------------------------------------------------------
__device__ float g_v [B_ * N_ * F_];                 // v fp32 (16 MB)
__device__ __nv_bfloat16 g_Sb[67108864];             // scores bf16 (128 MB)
__device__ __nv_bfloat16 g_xh [B_ * N_ * F_];        // x hi
__device__ __nv_bfloat16 g_xl [B_ * N_ * F_];        // x lo
__device__ __nv_bfloat16 g_xph[B_ * N_ * F_];        // xp hi
__device__ __nv_bfloat16 g_xpl[B_ * N_ * F_];
__device__ __nv_bfloat16 g_vth[B_ * F_ * N_];        // v^T hi  [b][256][4096]
__device__ __nv_bfloat16 g_vtl[B_ * F_ * N_];
__device__ __nv_bfloat16 g_Ph [67108864];            // softmax(S) hi (128 MB)
__device__ __nv_bfloat16 g_Pl [67108864];            // softmax(S) lo (128 MB)
__device__ __nv_bfloat16 g_wth [F_ * F_], g_wtl [F_ * F_];   // weight^T hi/lo
__device__ __nv_bfloat16 g_wnth[F_ * F_], g_wntl[F_ * F_];   // Wn_w^T hi/lo
__device__ float g_mean[B_ * MAXE * F_];
__device__ float g_ctx [B_ * MAXE];
__device__ float g_deg [MAXE];

// ---------------------------------------------------------------------------
// PTX helpers (base sm_100-safe: mma.sync / ldmatrix / cp.async)
// ---------------------------------------------------------------------------
__device__ __forceinline__ uint32_t smem_u32(const void* p) {
    uint32_t a;
    asm("{ .reg .u64 t; cvta.to.shared.u64 t, %1; cvt.u32.u64 %0, t; }"
        : "=r"(a) : "l"(p));
    return a;
}
__device__ __forceinline__ void cp_async16(uint32_t s, const void* g) {
    asm volatile("cp.async.cg.shared.global [%0], [%1], 16;\n"
        :: "r"(s), "l"((unsigned long long)__cvta_generic_to_global(g)) : "memory");
}
__device__ __forceinline__ void cp_commit() {
    asm volatile("cp.async.commit_group;\n" ::: "memory");
}
__device__ __forceinline__ void cp_wait0() {
    asm volatile("cp.async.wait_group 0;\n" ::: "memory");
}
__device__ __forceinline__ void cp_wait1() {
    asm volatile("cp.async.wait_group 1;\n" ::: "memory");
}
__device__ __forceinline__ void ldmatrix_x4(uint32_t* r, uint32_t addr) {
    asm volatile("ldmatrix.sync.aligned.m8n8.x4.shared.b16 {%0,%1,%2,%3}, [%4];\n"
        : "=r"(r[0]), "=r"(r[1]), "=r"(r[2]), "=r"(r[3]) : "r"(addr));
}
__device__ __forceinline__ void mma_bf16(float* d, const uint32_t* a,
                                         uint32_t b0, uint32_t b1) {
    asm volatile(
        "mma.sync.aligned.m16n8k16.row.col.f32.bf16.bf16.f32 "
        "{%0,%1,%2,%3}, {%4,%5,%6,%7}, {%8,%9}, {%0,%1,%2,%3};\n"
        : "+f"(d[0]), "+f"(d[1]), "+f"(d[2]), "+f"(d[3])
        : "r"(a[0]), "r"(a[1]), "r"(a[2]), "r"(a[3]), "r"(b0), "r"(b1));
}

// ---------------------------------------------------------------------------
// bf16 split GEMM via mma.sync: D[m][n] = scale*sum_k A[m,k]*B[n,k] (+bias)
// NPASS=3: AhBh + AlBh + AhBl.  NPASS=2: AhBh + AlBh.
// OMODE=0: fp32 out. OMODE=1: bf16 out. OMODE=2: bf16 hi/lo out.
// SYM=1: A==B from the same matrix; grid.x enumerates upper-triangle 128x128
//        tile pairs (NT=32 row blocks -> 528); each CTA writes its tile and
//        the transposed mirror (requires OMODE==1).
// CTA tile 128x128, K-chunk 64, 256 threads (8 warps 2m x 4n, warp 64x32).
// Smem: 3 stages x (A 16KB + B 16KB) = 96KB, XOR-swizzled for ldmatrix.
// Pipeline: depth-2 prefetch, cp.async.wait_group 1 (0 on the last chunk).
// ---------------------------------------------------------------------------
#define GEMM_SMEM (3 * 32768)

template <int NPASS, int OMODE, int SYM>
__global__ __launch_bounds__(256)
void gemm_bf16s(const __nv_bfloat16* __restrict__ Ah, const __nv_bfloat16* __restrict__ Al,
                const __nv_bfloat16* __restrict__ Bh, const __nv_bfloat16* __restrict__ Bl,
                void* __restrict__ C0p, void* __restrict__ C1p,
                const float* __restrict__ bias, int K, int ldc,
                long long sA, long long sB, long long sC, float scale)
{
    extern __shared__ __align__(16) char smem[];
    const uint32_t sbase = smem_u32(smem);
    const int tid = threadIdx.x;
    const int lane = tid & 31;
    const int wid = tid >> 5;
    const int wm = wid & 1;        // 2 warp rows  (64 rows each)
    const int wn = wid >> 1;       // 4 warp cols  (32 cols each)

    size_t Ms, Ns;
    int ibl = 0, jbl = 0;
    if (SYM) {
        const int NT = 32;
        int t = blockIdx.x;
        int i = (int)((2.f * NT + 1.f -
                       sqrtf((2.f * NT + 1.f) * (2.f * NT + 1.f) - 8.f * t)) * 0.5f);
        while ((i + 1) * NT - ((i + 1) * i) / 2 <= t) i++;
        while (i * NT - (i * (i - 1)) / 2 > t) i--;
        int j = i + (t - (i * NT - (i * (i - 1)) / 2));
        ibl = i; jbl = j;
        Ms = (size_t)i * 128;
        Ns = (size_t)j * 128;
    } else {
        Ms = (size_t)blockIdx.y * 128;
        Ns = (size_t)blockIdx.x * 128;
    }
    const int z = blockIdx.z;
    const __nv_bfloat16* pAh = Ah + (size_t)z * sA + Ms * K;
    const __nv_bfloat16* pAl = Al + (size_t)z * sA + Ms * K;
    const __nv_bfloat16* pBh = Bh + (size_t)z * sB + Ns * K;
    const __nv_bfloat16* pBl = Bl + (size_t)z * sB + Ns * K;

    const int KC = K >> 6;          // 64-wide K chunks per pass
    const int T = NPASS * KC;

    float acc[4][4][4];
#pragma unroll
    for (int i = 0; i < 4; i++)
#pragma unroll
        for (int j = 0; j < 4; j++)
#pragma unroll
            for (int k = 0; k < 4; k++) acc[i][j][k] = 0.f;

    auto load_chunk = [&](int t) {
        const int pass = t / KC;
        const int kk = (t - pass * KC) << 6;
        const __nv_bfloat16* pA = (pass == 1) ? pAl : pAh;
        const __nv_bfloat16* pB = (pass == 2) ? pBl : pBh;
        const uint32_t st = sbase + (t % 3) * 32768;
#pragma unroll
        for (int i = 0; i < 4; i++) {
            int idx = i * 256 + tid;
            int row = idx >> 3, c = idx & 7;
            uint32_t sa = st + row * 128 + ((c ^ (row & 7)) << 4);
            cp_async16(sa, pA + (size_t)row * K + kk + c * 8);
        }
#pragma unroll
        for (int i = 0; i < 4; i++) {
            int idx = i * 256 + tid;
            int row = idx >> 3, c = idx & 7;
            uint32_t sa = st + 16384 + row * 128 + ((c ^ (row & 7)) << 4);
            cp_async16(sa, pB + (size_t)row * K + kk + c * 8);
        }
        cp_commit();
    };

    load_chunk(0);
    load_chunk(1);

#pragma unroll 1
    for (int t = 0; t < T; t++) {
        if (t + 1 < T) cp_wait1(); else cp_wait0();
        __syncthreads();
        if (t + 2 < T) load_chunk(t + 2);

        const uint32_t Ab = sbase + (t % 3) * 32768;
        const uint32_t Bb = Ab + 16384;
#pragma unroll
        for (int ks = 0; ks < 4; ks++) {
            uint32_t afr[4][4];
#pragma unroll
            for (int mt = 0; mt < 4; mt++) {
                int arow = wm * 64 + mt * 16 + (lane & 15);
                int c = ks * 2 + (lane >> 4);
                ldmatrix_x4(afr[mt], Ab + arow * 128 + ((c ^ (arow & 7)) << 4));
            }
            uint32_t bfr[2][4];
#pragma unroll
            for (int np = 0; np < 2; np++) {
                int nrow = wn * 32 + np * 16 + (lane & 7) + ((lane >> 4) << 3);
                int c = ks * 2 + ((lane >> 3) & 1);
                ldmatrix_x4(bfr[np], Bb + nrow * 128 + ((c ^ (nrow & 7)) << 4));
            }
#pragma unroll
            for (int mt = 0; mt < 4; mt++)
#pragma unroll
                for (int nt = 0; nt < 4; nt++)
                    mma_bf16(acc[mt][nt], afr[mt],
                             bfr[nt >> 1][(nt & 1) * 2],
                             bfr[nt >> 1][(nt & 1) * 2 + 1]);
        }
    }

    // stage for SYM transpose (reuses pipeline smem after all compute done)
    __nv_bfloat16* stg = (__nv_bfloat16*)smem;     // [128][136]
    if (SYM) __syncthreads();

    // epilogue
    const int tg = lane >> 2, tq = lane & 3;
#pragma unroll
    for (int mt = 0; mt < 4; mt++) {
#pragma unroll
        for (int nt = 0; nt < 4; nt++) {
            int r0 = wm * 64 + mt * 16 + tg;
            int cc = wn * 32 + nt * 8 + tq * 2;
            float b0 = 0.f, b1 = 0.f;
            if (bias) { b0 = bias[Ns + cc]; b1 = bias[Ns + cc + 1]; }
            float v00 = acc[mt][nt][0] * scale + b0;
            float v01 = acc[mt][nt][1] * scale + b1;
            float v10 = acc[mt][nt][2] * scale + b0;
            float v11 = acc[mt][nt][3] * scale + b1;
            if (OMODE == 0) {
                float* pC = (float*)C0p + (size_t)z * sC + Ms * ldc + Ns;
                float2 w0 = { v00, v01 }, w1 = { v10, v11 };
                *(float2*)(pC + (size_t)r0 * ldc + cc)       = w0;
                *(float2*)(pC + (size_t)(r0 + 8) * ldc + cc) = w1;
            } else if (OMODE == 1) {
                __nv_bfloat16* pC = (__nv_bfloat16*)C0p + (size_t)z * sC + Ms * ldc + Ns;
                __nv_bfloat16 h00 = __float2bfloat16(v00), h01 = __float2bfloat16(v01);
                __nv_bfloat16 h10 = __float2bfloat16(v10), h11 = __float2bfloat16(v11);
                *(__nv_bfloat162*)(pC + (size_t)r0 * ldc + cc) = __nv_bfloat162(h00, h01);
                *(__nv_bfloat162*)(pC + (size_t)(r0 + 8) * ldc + cc) = __nv_bfloat162(h10, h11);
                if (SYM) {
                    stg[r0 * 136 + cc]           = h00;
                    stg[r0 * 136 + cc + 1]       = h01;
                    stg[(r0 + 8) * 136 + cc]     = h10;
                    stg[(r0 + 8) * 136 + cc + 1] = h11;
                }
            } else {
                __nv_bfloat16* pH = (__nv_bfloat16*)C0p + (size_t)z * sC + Ms * ldc + Ns;
                __nv_bfloat16* pL = (__nv_bfloat16*)C1p + (size_t)z * sC + Ms * ldc + Ns;
                __nv_bfloat16 h00 = __float2bfloat16(v00), h01 = __float2bfloat16(v01);
                __nv_bfloat16 h10 = __float2bfloat16(v10), h11 = __float2bfloat16(v11);
                *(__nv_bfloat162*)(pH + (size_t)r0 * ldc + cc) = __nv_bfloat162(h00, h01);
                *(__nv_bfloat162*)(pH + (size_t)(r0 + 8) * ldc + cc) = __nv_bfloat162(h10, h11);
                *(__nv_bfloat162*)(pL + (size_t)r0 * ldc + cc) =
                    __nv_bfloat162(__float2bfloat16(v00 - __bfloat162float(h00)),
                                   __float2bfloat16(v01 - __bfloat162float(h01)));
                *(__nv_bfloat162*)(pL + (size_t)(r0 + 8) * ldc + cc) =
                    __nv_bfloat162(__float2bfloat16(v10 - __bfloat162float(h10)),
                                   __float2bfloat16(v11 - __bfloat162float(h11)));
            }
        }
    }

    if (SYM && ibl != jbl) {
        __syncthreads();
        // write transposed mirror tile at row block jbl, col block ibl
        __nv_bfloat16* pT = (__nv_bfloat16*)C0p + (size_t)z * sC + Ns * ldc + Ms;
        const int orow = tid >> 1;        // 0..127 (transposed row = original col)
        const int half = tid & 1;
#pragma unroll
        for (int q = 0; q < 8; q++) {
            int c0 = half * 64 + q * 8;   // original-row index span
            __nv_bfloat16 tmp[8];
#pragma unroll
            for (int e = 0; e < 8; e++)
                tmp[e] = stg[(c0 + e) * 136 + orow];
            *(uint4*)(pT + (size_t)orow * ldc + c0) = *(uint4*)tmp;
        }
    }
}

// ---------------------------------------------------------------------------
// fp32 -> (bf16 hi, bf16 lo) split, 4 elements/thread
// ---------------------------------------------------------------------------
__global__ __launch_bounds__(256)
void conv_split(const float* __restrict__ in, __nv_bfloat16* __restrict__ hi,
                __nv_bfloat16* __restrict__ lo, int n)
{
    int i = (blockIdx.x * 256 + threadIdx.x) * 4;
    if (i >= n) return;
    float4 v = *(const float4*)(in + i);
    __nv_bfloat16 h0 = __float2bfloat16(v.x), h1 = __float2bfloat16(v.y);
    __nv_bfloat16 h2 = __float2bfloat16(v.z), h3 = __float2bfloat16(v.w);
    __nv_bfloat162 ph0(h0, h1), ph1(h2, h3);
    __nv_bfloat162 pl0(__float2bfloat16(v.x - __bfloat162float(h0)),
                       __float2bfloat16(v.y - __bfloat162float(h1)));
    __nv_bfloat162 pl1(__float2bfloat16(v.z - __bfloat162float(h2)),
                       __float2bfloat16(v.w - __bfloat162float(h3)));
    *(__nv_bfloat162*)(hi + i)     = ph0;
    *(__nv_bfloat162*)(hi + i + 2) = ph1;
    *(__nv_bfloat162*)(lo + i)     = pl0;
    *(__nv_bfloat162*)(lo + i + 2) = pl1;
}

// ---------------------------------------------------------------------------
// transpose + split: in [R][C] fp32 -> out [C][R] bf16 hi/lo. block (32,8)
// ---------------------------------------------------------------------------
__global__ __launch_bounds__(256)
void transpose_split(const float* __restrict__ in, __nv_bfloat16* __restrict__ oh,
                     __nv_bfloat16* __restrict__ ol, int R, int C,
                     long long sIn, long long sOut)
{
    __shared__ float tile[32][33];
    const int c0 = blockIdx.x * 32, r0 = blockIdx.y * 32, z = blockIdx.z;
    in += (size_t)z * sIn; oh += (size_t)z * sOut; ol += (size_t)z * sOut;
    const int tx = threadIdx.x, ty = threadIdx.y;
#pragma unroll
    for (int j = 0; j < 4; j++)
        tile[ty + 8 * j][tx] = in[(size_t)(r0 + ty + 8 * j) * C + c0 + tx];
    __syncthreads();
#pragma unroll
    for (int j = 0; j < 4; j++) {
        float v = tile[tx][ty + 8 * j];
        __nv_bfloat16 h = __float2bfloat16(v);
        size_t o = (size_t)(c0 + ty + 8 * j) * R + r0 + tx;
        oh[o] = h;
        ol[o] = __float2bfloat16(v - __bfloat162float(h));
    }
}

// ---------------------------------------------------------------------------
// Row softmax on bf16 S -> bf16 hi/lo P. grid (4096, 1, B), 256 threads.
// Fully 16B-vectorized: each thread owns 16 contiguous elems (2 x uint4).
// ---------------------------------------------------------------------------
__global__ __launch_bounds__(256)
void softmax_split_b(const __nv_bfloat16* __restrict__ S,
                     __nv_bfloat16* __restrict__ Ph, __nv_bfloat16* __restrict__ Pl)
{
    const size_t row = (size_t)blockIdx.z * N_ + blockIdx.x;
    const uint4* r4 = (const uint4*)(S + row * N_);      // 512 uint4 per row
    uint4* ph4 = (uint4*)(Ph + row * N_);
    uint4* pl4 = (uint4*)(Pl + row * N_);
    const int tid = threadIdx.x, lane = tid & 31, wid = tid >> 5;
    __shared__ float red[8];
    __shared__ float bval;

    uint4 u[2];
    u[0] = r4[tid];
    u[1] = r4[tid + 256];
    float v[16];
#pragma unroll
    for (int q = 0; q < 2; q++) {
        const uint32_t* w = (const uint32_t*)&u[q];
#pragma unroll
        for (int j = 0; j < 4; j++) {
            float2 f = __bfloat1622float2(*(const __nv_bfloat162*)&w[j]);
            v[q * 8 + j * 2]     = f.x;
            v[q * 8 + j * 2 + 1] = f.y;
        }
    }

    float mx = v[0];
#pragma unroll
    for (int j = 1; j < 16; j++) mx = fmaxf(mx, v[j]);
#pragma unroll
    for (int off = 16; off; off >>= 1)
        mx = fmaxf(mx, __shfl_xor_sync(0xffffffffu, mx, off));
    if (lane == 0) red[wid] = mx;
    __syncthreads();
    if (tid == 0) {
        float m = red[0];
#pragma unroll
        for (int i = 1; i < 8; i++) m = fmaxf(m, red[i]);
        bval = m;
    }
    __syncthreads();
    mx = bval;

    float s = 0.f;
#pragma unroll
    for (int j = 0; j < 16; j++) { v[j] = __expf(v[j] - mx); s += v[j]; }
#pragma unroll
    for (int off = 16; off; off >>= 1)
        s += __shfl_xor_sync(0xffffffffu, s, off);
    if (lane == 0) red[wid] = s;
    __syncthreads();
    if (tid == 0) {
        float t = 0.f;
#pragma unroll
        for (int i = 0; i < 8; i++) t += red[i];
        bval = 1.f / t;
    }
    __syncthreads();
    const float inv = bval;

    uint4 oh[2], ol[2];
#pragma unroll
    for (int q = 0; q < 2; q++) {
        uint32_t* wh = (uint32_t*)&oh[q];
        uint32_t* wl = (uint32_t*)&ol[q];
#pragma unroll
        for (int j = 0; j < 4; j++) {
            float a = v[q * 8 + j * 2] * inv;
            float b = v[q * 8 + j * 2 + 1] * inv;
            __nv_bfloat16 ha = __float2bfloat16(a), hb = __float2bfloat16(b);
            __nv_bfloat162 hp(ha, hb);
            __nv_bfloat162 lp(__float2bfloat16(a - __bfloat162float(ha)),
                              __float2bfloat16(b - __bfloat162float(hb)));
            wh[j] = *(uint32_t*)&hp;
            wl[j] = *(uint32_t*)&lp;
        }
    }
    ph4[tid]       = oh[0];
    ph4[tid + 256] = oh[1];
    pl4[tid]       = ol[0];
    pl4[tid + 256] = ol[1];
}

// ---------------------------------------------------------------------------
// Hyperedge branch
// ---------------------------------------------------------------------------
__global__ __launch_bounds__(256)
void edge_mean_kernel(const float* __restrict__ x, const int* __restrict__ Hm)
{
    const int e = blockIdx.x, b = blockIdx.y, f = threadIdx.x;
    const float* xb = x + (size_t)b * N_ * F_;
    float sum = 0.f;
    int cnt = 0;
    for (int n = 0; n < N_; n++) {
        if (Hm[(size_t)n * E_ + e]) {
            sum += xb[(size_t)n * F_ + f];
            cnt++;
        }
    }
    const float deg = (float)cnt;
    g_mean[((size_t)b * MAXE + e) * F_ + f] = sum / fmaxf(deg, 1.0f);
    if (f == 0 && b == 0) g_deg[e] = deg;
}

__global__ __launch_bounds__(128)
void ctx_kernel(const float* __restrict__ m1w, const float* __restrict__ m1b,
                const float* __restrict__ m2w, const float* __restrict__ m2b,
                const float* __restrict__ m3w, const float* __restrict__ m3b)
{
    const int e = blockIdx.x, b = blockIdx.y, t = threadIdx.x;
    __shared__ float ms[F_];
    __shared__ float h1[H1_];
    __shared__ float h2[H2_];
    __shared__ float red[4];

    const float* mp = g_mean + ((size_t)b * MAXE + e) * F_;
    ms[t]       = mp[t];
    ms[t + 128] = mp[t + 128];
    __syncthreads();

    float s = m1b[t];
    for (int k = 0; k < F_; k++) s += ms[k] * m1w[k * H1_ + t];
    h1[t] = fmaxf(s, 0.f);
    __syncthreads();

    if (t < H2_) {
        float s2 = m2b[t];
        for (int k = 0; k < H1_; k++) s2 += h1[k] * m2w[k * H2_ + t];
        h2[t] = fmaxf(s2, 0.f);
    }
    __syncthreads();

    float p = (t < H2_) ? h2[t] * m3w[t] : 0.f;
#pragma unroll
    for (int off = 16; off; off >>= 1)
        p += __shfl_xor_sync(0xffffffffu, p, off);
    if ((t & 31) == 0) red[t >> 5] = p;
    __syncthreads();
    if (t == 0)
        g_ctx[b * MAXE + e] = red[0] + red[1] + red[2] + red[3] + m3b[0];
}

__global__ __launch_bounds__(256)
void aw_kernel(const float* __restrict__ x, const int* __restrict__ Hm,
               const float* __restrict__ cw, const float* __restrict__ cb,
               const float* __restrict__ hb, const float* __restrict__ alpha,
               float* __restrict__ out)
{
    const int n = blockIdx.x, b = blockIdx.y, t = threadIdx.x;
    __shared__ float red[8];
    __shared__ float compat_s;

    float p = x[((size_t)b * N_ + n) * F_ + t] * cw[t];
#pragma unroll
    for (int off = 16; off; off >>= 1)
        p += __shfl_xor_sync(0xffffffffu, p, off);
    if ((t & 31) == 0) red[t >> 5] = p;
    __syncthreads();
    if (t == 0) {
        float s = 0.f;
#pragma unroll
        for (int i = 0; i < 8; i++) s += red[i];
        compat_s = s + cb[0] + hb[0];
    }
    __syncthreads();

    float val = 0.f;
    if (t < MAXE) {
        if (Hm[(size_t)n * E_ + t] && g_deg[t] > 1.0f) {
            float z = compat_s + alpha[0] * g_ctx[b * MAXE + t];
            val = 1.f / (1.f + __expf(-z));
        }
    }
    out[((size_t)b * N_ + n) * OUTC + t] = val;
}

// ---------------------------------------------------------------------------
// Launch
// ---------------------------------------------------------------------------
extern "C" void kernel_launch(void* const* d_in, const int* in_sizes, int n_in,
                              void* d_out, int out_size)
{
    const float* x      = (const float*)d_in[0];
    const int*   Hm     = (const int*)  d_in[1];
    const float* weight = (const float*)d_in[2];
    const float* bias   = (const float*)d_in[3];
    const float* Wn_w   = (const float*)d_in[4];
    const float* Wn_b   = (const float*)d_in[5];
    const float* m1_w   = (const float*)d_in[6];
    const float* m1_b   = (const float*)d_in[7];
    const float* m2_w   = (const float*)d_in[8];
    const float* m2_b   = (const float*)d_in[9];
    const float* m3_w   = (const float*)d_in[10];
    const float* m3_b   = (const float*)d_in[11];
    const float* c_w    = (const float*)d_in[12];
    const float* c_b    = (const float*)d_in[13];
    const float* hedgeb = (const float*)d_in[14];
    const float* alpha  = (const float*)d_in[15];
    float* out = (float*)d_out;

    float* v;
    __nv_bfloat16 *Sb, *xh, *xl, *xph, *xpl, *vth, *vtl, *Ph, *Pl;
    __nv_bfloat16 *wth, *wtl, *wnth, *wntl;
    cudaGetSymbolAddress((void**)&v,   g_v);
    cudaGetSymbolAddress((void**)&Sb,  g_Sb);
    cudaGetSymbolAddress((void**)&xh,  g_xh);
    cudaGetSymbolAddress((void**)&xl,  g_xl);
    cudaGetSymbolAddress((void**)&xph, g_xph);
    cudaGetSymbolAddress((void**)&xpl, g_xpl);
    cudaGetSymbolAddress((void**)&vth, g_vth);
    cudaGetSymbolAddress((void**)&vtl, g_vtl);
    cudaGetSymbolAddress((void**)&Ph,  g_Ph);
    cudaGetSymbolAddress((void**)&Pl,  g_Pl);
    cudaGetSymbolAddress((void**)&wth, g_wth);
    cudaGetSymbolAddress((void**)&wtl, g_wtl);
    cudaGetSymbolAddress((void**)&wnth, g_wnth);
    cudaGetSymbolAddress((void**)&wntl, g_wntl);

    cudaFuncSetAttribute(gemm_bf16s<3, 0, 0>,
                         cudaFuncAttributeMaxDynamicSharedMemorySize, GEMM_SMEM);
    cudaFuncSetAttribute(gemm_bf16s<3, 2, 0>,
                         cudaFuncAttributeMaxDynamicSharedMemorySize, GEMM_SMEM);
    cudaFuncSetAttribute(gemm_bf16s<2, 1, 1>,
                         cudaFuncAttributeMaxDynamicSharedMemorySize, GEMM_SMEM);

    const int nx = B_ * N_ * F_;   // 4M elements

    // hyperedge branch (independent)
    edge_mean_kernel<<<dim3(MAXE, B_), 256>>>(x, Hm);
    ctx_kernel<<<dim3(MAXE, B_), 128>>>(m1_w, m1_b, m2_w, m2_b, m3_w, m3_b);
    aw_kernel<<<dim3(N_, B_), 256>>>(x, Hm, c_w, c_b, hedgeb, alpha, out);

    // input conversions
    conv_split<<<nx / 4 / 256, 256>>>(x, xh, xl, nx);
    transpose_split<<<dim3(8, 8, 1), dim3(32, 8)>>>(weight, wth, wtl, F_, F_, 0, 0);
    transpose_split<<<dim3(8, 8, 1), dim3(32, 8)>>>(Wn_w, wnth, wntl, F_, F_, 0, 0);

    // projections: xp = x@Wn_w + Wn_b (split emitted directly) ; v = x@weight (fp32)
    gemm_bf16s<3, 2, 0><<<dim3(F_ / 128, (B_ * N_) / 128, 1), 256, GEMM_SMEM>>>(
        xh, xl, wnth, wntl, xph, xpl, Wn_b, F_, F_, 0, 0, 0, 1.0f);
    gemm_bf16s<3, 0, 0><<<dim3(F_ / 128, (B_ * N_) / 128, 1), 256, GEMM_SMEM>>>(
        xh, xl, wth, wtl, v, nullptr, nullptr, F_, F_, 0, 0, 0, 1.0f);

    // v transposed per batch -> bf16 hi/lo
    transpose_split<<<dim3(F_ / 32, N_ / 32, B_), dim3(32, 8)>>>(
        v, vth, vtl, N_, F_, (long long)N_ * F_, (long long)F_ * N_);

    // S = xp @ xp^T / 16 -> bf16, symmetric: 528 upper-triangle tiles + mirror
    gemm_bf16s<2, 1, 1><<<dim3(528, 1, B_), 256, GEMM_SMEM>>>(
        xph, xpl, xph, xpl, Sb, nullptr, nullptr, F_, N_,
        (long long)N_ * F_, (long long)N_ * F_, (long long)N_ * N_, 0.0625f);

    // P = softmax(S) -> bf16 hi/lo
    softmax_split_b<<<dim3(N_, 1, B_), 256>>>(Sb, Ph, Pl);

    // y = P @ V + bias -> out[..., E:E+F]
    gemm_bf16s<3, 0, 0><<<dim3(F_ / 128, N_ / 128, B_), 256, GEMM_SMEM>>>(
        Ph, Pl, vth, vtl, out + E_, nullptr, bias, N_, OUTC,
        (long long)N_ * N_, (long long)F_ * N_, (long long)N_ * OUTC, 1.0f);
}